// round 12
// baseline (speedup 1.0000x reference)
#include <cuda_runtime.h>
#include <cuda_fp16.h>
#include <math.h>
#include <stdint.h>

#define N_ATOMS 100000
#define IN_F    1008
#define KPAD    1024
#define H1      256
#define H2      192
#define H3      160
#define CALPHA  0.1f
#define MT      128
#define TPB     512
#define NT_MAX  ((N_ATOMS + MT - 1) / MT)       // 782
#define PAD_MAX ((NT_MAX + 5) * MT)

// ---------------- device scratch (static, no allocations) ----------------
__device__ int g_type[N_ATOMS];
__device__ int g_sorted[PAD_MAX];
__device__ int g_counts[5], g_poff[5], g_cursor[5], g_is64;
// fp16 weights, uint4-fragment order: [t][kc][n8][kp(2)][lane] uint4
__device__ uint2 g_W16_1[5 * H1 * KPAD / 4];
__device__ uint2 g_W16_2[5 * H2 * H1 / 4];
__device__ uint2 g_W16_3[5 * H3 * H2 / 4];
// fp16 fragment-order h1 [tile][ks(16)][bm(8)][lane(32)]
__device__ uint4 g_H1f[(size_t)(NT_MAX + 5) * 16 * 8 * 32];

// ---------------- helpers ----------------
__device__ __forceinline__ float celu_f(float x) {
    return x > 0.0f ? x : CALPHA * expm1f(x * (1.0f / CALPHA));
}
__device__ __forceinline__ uint32_t pack2(float a, float b) {
    __half2 h = __floats2half2_rn(a, b);
    return *reinterpret_cast<uint32_t*>(&h);
}
__device__ __forceinline__ void cp16(uint32_t dst, const void* src) {
    asm volatile("cp.async.cg.shared.global [%0], [%1], 16;"
                 :: "r"(dst), "l"(src) : "memory");
}
__device__ __forceinline__ void cp16z(uint32_t dst, const void* src, int valid) {
    asm volatile("cp.async.cg.shared.global [%0], [%1], 16, %2;"
                 :: "r"(dst), "l"(src), "r"(valid ? 16 : 0) : "memory");
}
#define CP_COMMIT() asm volatile("cp.async.commit_group;" ::: "memory")
#define CP_WAIT0()  asm volatile("cp.async.wait_group 0;" ::: "memory")
#define CP_WAIT1()  asm volatile("cp.async.wait_group 1;" ::: "memory")

#define MMA16(d, a, b0, b1) \
    asm volatile("mma.sync.aligned.m16n8k16.row.col.f32.f16.f16.f32 " \
                 "{%0,%1,%2,%3},{%4,%5,%6,%7},{%8,%9},{%0,%1,%2,%3};" \
                 : "+f"((d)[0]), "+f"((d)[1]), "+f"((d)[2]), "+f"((d)[3]) \
                 : "r"((a).x), "r"((a).y), "r"((a).z), "r"((a).w), \
                   "r"(b0), "r"(b1))

__device__ __forceinline__ uint4 ldsm4(uint32_t addr) {
    uint4 v;
    asm volatile("ldmatrix.sync.aligned.m8n8.x4.shared.b16 {%0,%1,%2,%3}, [%4];"
                 : "=r"(v.x), "=r"(v.y), "=r"(v.z), "=r"(v.w) : "r"(addr));
    return v;
}

// ---------------- plumbing ----------------
__global__ void k_init(const int* __restrict__ z32, float* out, int n_out) {
    int i = blockIdx.x * blockDim.x + threadIdx.x;
    if (i < n_out) out[i] = 0.0f;
    if (i < PAD_MAX) g_sorted[i] = -1;
    if (i == 0) {
        g_is64 = (z32[1] == 0 && z32[3] == 0 && z32[5] == 0 && z32[7] == 0) ? 1 : 0;
        for (int t = 0; t < 5; t++) { g_counts[t] = 0; g_cursor[t] = 0; }
    }
}
__device__ __forceinline__ int z_to_type(int zv) {
    return (zv == 1) ? 0 : (zv == 6) ? 1 : (zv == 7) ? 2 : (zv == 8) ? 3 : 4;
}

// weight permute into uint4-fragment order (KC=64), fp16
template<int KC>
__device__ __forceinline__ void prep_w(uint2* dst, const float* src,
                                       int NN, int KTOT, int KIN, int i) {
    constexpr int KS = KC / 16;
    const int lane = i & 31;
    const int ks   = (i >> 5) % KS;
    int rest = i / (32 * KS);
    const int n8 = rest % (NN / 8); rest /= (NN / 8);
    const int kc = rest % (KTOT / KC);
    const int t  = rest / (KTOT / KC);
    const int n = n8 * 8 + (lane >> 2);
    const int k0 = kc * KC + ks * 16 + 2 * (lane & 3);
    const int k1 = k0 + 8;
    const float* W = src + (size_t)t * KIN * NN;
    float v00 = (k0 < KIN)     ? W[(size_t)k0 * NN + n]       : 0.0f;
    float v01 = (k0 + 1 < KIN) ? W[(size_t)(k0 + 1) * NN + n] : 0.0f;
    float v10 = (k1 < KIN)     ? W[(size_t)k1 * NN + n]       : 0.0f;
    float v11 = (k1 + 1 < KIN) ? W[(size_t)(k1 + 1) * NN + n] : 0.0f;
    const int group = (t * (KTOT / KC) + kc) * (NN / 8) + n8;
    dst[(size_t)group * (KS * 32) + (ks >> 1) * 64 + lane * 2 + (ks & 1)] =
        make_uint2(pack2(v00, v01), pack2(v10, v11));
}

__global__ void k_count_prep(const int* __restrict__ z32,
                             const float* __restrict__ W1,
                             const float* __restrict__ W2,
                             const float* __restrict__ W3) {
    int i = blockIdx.x * blockDim.x + threadIdx.x;
    if (blockIdx.y == 0) {
        if (i >= N_ATOMS) return;
        int zv = g_is64 ? z32[2 * i] : z32[i];
        int t = z_to_type(zv);
        g_type[i] = t;
        atomicAdd(&g_counts[t], 1);
    } else {
        const int n1 = 5 * H1 * KPAD / 4, n2 = 5 * H2 * H1 / 4, n3 = 5 * H3 * H2 / 4;
        if (i < n1) prep_w<64>(g_W16_1, W1, H1, KPAD, IN_F, i);
        else if (i < n1 + n2) prep_w<64>(g_W16_2, W2, H2, H1, H1, i - n1);
        else if (i < n1 + n2 + n3) prep_w<64>(g_W16_3, W3, H3, H2, H2, i - n1 - n2);
    }
}

__global__ void k_scatter() {
    int i = blockIdx.x * blockDim.x + threadIdx.x;
    int off[5]; int acc = 0;
#pragma unroll
    for (int t = 0; t < 5; t++) {
        off[t] = acc;
        acc += ((g_counts[t] + MT - 1) / MT) * MT;
    }
    if (i == 0) {
#pragma unroll
        for (int t = 0; t < 5; t++) g_poff[t] = off[t];
    }
    if (i >= N_ATOMS) return;
    int t = g_type[i];
    int pos = off[t] + atomicAdd(&g_cursor[t], 1);
    g_sorted[pos] = i;
}

// ================= GEMM 1 (N-split: each CTA does 128 x 128 x 1024) =================
// grid (NT, 2, 5): blockIdx.y = N-half, blockIdx.z = type.
// 512 threads = 16 warps as 4(M) x 4(N); warp tile 32 x 32; K-chunks of 64.
// A32: 128 rows x 64 fp32 (dbuf), float4 slot jsw = fq ^ (r&15)
// A16: 128 rows x 64 halves (single), 16B chunk j swizzled jsw = j ^ (r&7)
#define G1_SM_A32 0                       // 2*32768 = 65536
#define G1_SM_A16 65536                   // 16384
#define G1_SM_B   81920                   // 2*1024 uint4 = 32768
#define G1_SM_IDS 114688                  // 128 ints
#define G1_SM_TOTAL 115200

__global__ void __launch_bounds__(TPB)
k_gemm1(const float* __restrict__ feat, const float* __restrict__ b1)
{
    constexpr int NCH = KPAD / 64;        // 16
    constexpr int NT8 = 4;                // 4 n8-tiles per warp (32 cols)

    const int t = blockIdx.z;
    const int nh = blockIdx.y;            // N-half: 0 or 1
    const int cnt = g_counts[t];
    const int start = blockIdx.x * MT;
    if (start >= cnt) return;
    const int tile = (g_poff[t] >> 7) + blockIdx.x;

    extern __shared__ __align__(16) char smem[];
    float* sA32 = reinterpret_cast<float*>(smem + G1_SM_A32);
    uint4* sB4  = reinterpret_cast<uint4*>(smem + G1_SM_B);
    int*   sids = reinterpret_cast<int*>(smem + G1_SM_IDS);

    const int tid = threadIdx.x;
    const int wid = tid >> 5, lane = tid & 31;
    const int wm = wid & 3, wn = wid >> 2;
    const int tig = lane & 3;

    if (tid < MT) sids[tid] = g_sorted[tile * MT + tid];
    __syncthreads();

    const uint32_t sA32_u = (uint32_t)__cvta_generic_to_shared(smem + G1_SM_A32);
    const uint32_t sA16_u = (uint32_t)__cvta_generic_to_shared(smem + G1_SM_A16);
    const uint32_t sB_u   = (uint32_t)__cvta_generic_to_shared(sB4);
    const uint4* Bt = reinterpret_cast<const uint4*>(g_W16_1)
                      + (size_t)t * (H1 * KPAD / 8) + nh * 1024;

    const int crow = tid & 127;
    const int Q = tid >> 7;
    const int lrow = wm * 32 + (lane & 15);
    const int ljhi = lane >> 4;
    const int lxor = lrow & 7;

    float acc[2][NT8][4];
#pragma unroll
    for (int i = 0; i < 2; i++)
#pragma unroll
        for (int j = 0; j < NT8; j++)
#pragma unroll
            for (int q = 0; q < 4; q++) acc[i][j][q] = 0.0f;

    auto issue = [&](int c) {
        const int s = c & 1;
#pragma unroll
        for (int q = tid; q < MT * 16; q += TPB) {
            const int r = q >> 4, fq = q & 15;
            const int id = sids[r];
            const int k = c * 64 + fq * 4;
            const int v = (id >= 0) && (k < IN_F);
            const float* src = feat + (v ? ((size_t)id * IN_F + k) : 0);
            const int jsw = fq ^ (r & 15);
            cp16z(sA32_u + ((((s * MT + r) << 6) + (jsw << 2)) << 2), src, v);
        }
        const uint4* b = Bt + (size_t)c * 2048;
#pragma unroll
        for (int q = tid; q < 1024; q += TPB)
            cp16(sB_u + ((s * 1024 + q) << 4), b + q);
        CP_COMMIT();
    };

    issue(0);
    for (int c = 0; c < NCH; c++) {
        const int s = c & 1;
        CP_WAIT0();
        __syncthreads();

        // convert pass: A32 stage s -> A16
        {
            const float* A32 = sA32 + s * MT * 64 + crow * 64;
            float4 f0 = *reinterpret_cast<const float4*>(A32 + (((4 * Q + 0) ^ (crow & 15)) << 2));
            float4 f1 = *reinterpret_cast<const float4*>(A32 + (((4 * Q + 1) ^ (crow & 15)) << 2));
            float4 f2 = *reinterpret_cast<const float4*>(A32 + (((4 * Q + 2) ^ (crow & 15)) << 2));
            float4 f3 = *reinterpret_cast<const float4*>(A32 + (((4 * Q + 3) ^ (crow & 15)) << 2));
            uint4 v0, v1;
            v0.x = pack2(f0.x, f0.y); v0.y = pack2(f0.z, f0.w);
            v0.z = pack2(f1.x, f1.y); v0.w = pack2(f1.z, f1.w);
            v1.x = pack2(f2.x, f2.y); v1.y = pack2(f2.z, f2.w);
            v1.z = pack2(f3.x, f3.y); v1.w = pack2(f3.z, f3.w);
            const uint32_t d0 = sA16_u + crow * 128 + (((2 * Q) ^ (crow & 7)) << 4);
            const uint32_t d1 = sA16_u + crow * 128 + (((2 * Q + 1) ^ (crow & 7)) << 4);
            asm volatile("st.shared.v4.b32 [%0], {%1,%2,%3,%4};"
                         :: "r"(d0), "r"(v0.x), "r"(v0.y), "r"(v0.z), "r"(v0.w));
            asm volatile("st.shared.v4.b32 [%0], {%1,%2,%3,%4};"
                         :: "r"(d1), "r"(v1.x), "r"(v1.y), "r"(v1.z), "r"(v1.w));
        }
        __syncthreads();

        if (c + 1 < NCH) issue(c + 1);

        const uint4* B = sB4 + s * 1024;
#pragma unroll
        for (int kp = 0; kp < 2; kp++) {
            uint4 av0[2], av1[2];
#pragma unroll
            for (int mt = 0; mt < 2; mt++) {
                const int row = lrow + mt * 16;
                const int j0 = ((2 * kp) * 2 + ljhi) ^ lxor;
                const int j1 = ((2 * kp + 1) * 2 + ljhi) ^ lxor;
                av0[mt] = ldsm4(sA16_u + row * 128 + j0 * 16);
                av1[mt] = ldsm4(sA16_u + row * 128 + j1 * 16);
            }
#pragma unroll
            for (int nt = 0; nt < NT8; nt++) {
                const uint4 bq = B[((wn * NT8 + nt) << 6) + (kp << 5) + lane];
#pragma unroll
                for (int mt = 0; mt < 2; mt++) {
                    MMA16(acc[mt][nt], av0[mt], bq.x, bq.y);
                    MMA16(acc[mt][nt], av1[mt], bq.z, bq.w);
                }
            }
        }
    }

    // epilogue: bias+celu -> h1 fragments [ks16][bm8][lane32]; this CTA owns ks nh*8..nh*8+7
    uint4* Hout = g_H1f + (size_t)tile * 16 * 256;
    const float* bv = b1 + t * H1;
#pragma unroll
    for (int mt = 0; mt < 2; mt++) {
#pragma unroll
        for (int ntp = 0; ntp < NT8 / 2; ntp++) {
            const int nt = 2 * ntp;
            const int c0 = nh * 128 + wn * 32 + nt * 8 + 2 * tig;
            const int c1 = c0 + 8;
            const float bb0 = __ldg(bv + c0), bb1 = __ldg(bv + c0 + 1);
            const float bb2 = __ldg(bv + c1), bb3 = __ldg(bv + c1 + 1);
            uint4 v;
            v.x = pack2(celu_f(acc[mt][nt][0] + bb0),     celu_f(acc[mt][nt][1] + bb1));
            v.y = pack2(celu_f(acc[mt][nt][2] + bb0),     celu_f(acc[mt][nt][3] + bb1));
            v.z = pack2(celu_f(acc[mt][nt + 1][0] + bb2), celu_f(acc[mt][nt + 1][1] + bb3));
            v.w = pack2(celu_f(acc[mt][nt + 1][2] + bb2), celu_f(acc[mt][nt + 1][3] + bb3));
            const int ks = nh * 8 + wn * 2 + ntp;
            const int bm = wm * 2 + mt;
            Hout[(ks * 8 + bm) * 32 + lane] = v;
        }
    }
}

// ================= GEMM 2+3 fused: h1 -> h2 (smem) -> out =================
#define G2_SM_A   0
#define G2_SM_B   32768
#define G2_SM_H2  81920
#define G2_SM_IDS 131072
#define G2_SM_TOTAL 131584

__global__ void __launch_bounds__(TPB)
k_gemm23(const int* __restrict__ batch32,
         const float* __restrict__ b2, const float* __restrict__ b3,
         const float* __restrict__ W4, const float* __restrict__ b4,
         float* __restrict__ out)
{
    const int t = blockIdx.y;
    const int cnt = g_counts[t];
    const int start = blockIdx.x * MT;
    if (start >= cnt) return;
    const int nact = min(MT, cnt - start);
    const int tile = (g_poff[t] >> 7) + blockIdx.x;

    extern __shared__ __align__(16) char smem[];
    uint4* sA   = reinterpret_cast<uint4*>(smem + G2_SM_A);
    uint4* sB4  = reinterpret_cast<uint4*>(smem + G2_SM_B);
    uint4* sH2  = reinterpret_cast<uint4*>(smem + G2_SM_H2);
    int*   sids = reinterpret_cast<int*>(smem + G2_SM_IDS);

    const int tid = threadIdx.x;
    const int wid = tid >> 5, lane = tid & 31;
    const int wm = wid & 3, wn = wid >> 2;
    const int g = lane >> 2, tig = lane & 3;

    if (tid < MT) sids[tid] = g_sorted[tile * MT + tid];
    __syncthreads();

    const uint32_t sA_u = (uint32_t)__cvta_generic_to_shared(sA);
    const uint32_t sB_u = (uint32_t)__cvta_generic_to_shared(sB4);

    // ---------- Layer 2: A = g_H1f, B = g_W16_2, NN=192, K=256 ----------
    {
        constexpr int NCH = 4, NT8 = 6, BCH = H2 * 8;
        const uint4* Asrc = g_H1f + (size_t)tile * 16 * 256;
        const uint4* Bt = reinterpret_cast<const uint4*>(g_W16_2) + (size_t)t * (H2 * H1 / 8);

        float acc[2][NT8][4];
#pragma unroll
        for (int i = 0; i < 2; i++)
#pragma unroll
            for (int j = 0; j < NT8; j++)
#pragma unroll
                for (int q = 0; q < 4; q++) acc[i][j][q] = 0.0f;

        auto issue = [&](int c) {
            const int s = c & 1;
            const uint4* a = Asrc + c * 1024;
#pragma unroll
            for (int q = tid; q < 1024; q += TPB)
                cp16(sA_u + ((s * 1024 + q) << 4), a + q);
            const uint4* b = Bt + (size_t)c * BCH;
#pragma unroll
            for (int q = tid; q < BCH; q += TPB)
                cp16(sB_u + ((s * BCH + q) << 4), b + q);
            CP_COMMIT();
        };

        issue(0);
        for (int c = 0; c < NCH; c++) {
            if (c + 1 < NCH) { issue(c + 1); CP_WAIT1(); }
            else             { CP_WAIT0(); }
            __syncthreads();
            const uint4* A = sA + (c & 1) * 1024;
            const uint4* B = sB4 + (c & 1) * BCH;
#pragma unroll
            for (int kp = 0; kp < 2; kp++) {
                uint4 av0[2], av1[2];
#pragma unroll
                for (int mt = 0; mt < 2; mt++) {
                    av0[mt] = A[((2 * kp) * 8 + wm * 2 + mt) * 32 + lane];
                    av1[mt] = A[((2 * kp + 1) * 8 + wm * 2 + mt) * 32 + lane];
                }
#pragma unroll
                for (int nt = 0; nt < NT8; nt++) {
                    const uint4 bq = B[((wn * NT8 + nt) << 6) + (kp << 5) + lane];
#pragma unroll
                    for (int mt = 0; mt < 2; mt++) {
                        MMA16(acc[mt][nt], av0[mt], bq.x, bq.y);
                        MMA16(acc[mt][nt], av1[mt], bq.z, bq.w);
                    }
                }
            }
            __syncthreads();
        }

        const float* bv = b2 + t * H2;
#pragma unroll
        for (int mt = 0; mt < 2; mt++) {
#pragma unroll
            for (int ntp = 0; ntp < NT8 / 2; ntp++) {
                const int nt = 2 * ntp;
                const int c0 = wn * (H2 / 4) + nt * 8 + 2 * tig;
                const int c1 = c0 + 8;
                const float bb0 = __ldg(bv + c0), bb1 = __ldg(bv + c0 + 1);
                const float bb2 = __ldg(bv + c1), bb3 = __ldg(bv + c1 + 1);
                uint4 v;
                v.x = pack2(celu_f(acc[mt][nt][0] + bb0),     celu_f(acc[mt][nt][1] + bb1));
                v.y = pack2(celu_f(acc[mt][nt][2] + bb0),     celu_f(acc[mt][nt][3] + bb1));
                v.z = pack2(celu_f(acc[mt][nt + 1][0] + bb2), celu_f(acc[mt][nt + 1][1] + bb3));
                v.w = pack2(celu_f(acc[mt][nt + 1][2] + bb2), celu_f(acc[mt][nt + 1][3] + bb3));
                const int ks = wn * (NT8 / 2) + ntp;
                const int bm = wm * 2 + mt;
                sH2[(ks * 8 + bm) * 32 + lane] = v;
            }
        }
    }
    __syncthreads();

    // ---------- Layer 3 + 4: A = sH2, B = g_W16_3, NN=160, K=192 ----------
    {
        constexpr int NCH = 3, NT8 = 5, BCH = H3 * 8;
        const uint4* Bt = reinterpret_cast<const uint4*>(g_W16_3) + (size_t)t * (H3 * H2 / 8);

        float acc[2][NT8][4];
#pragma unroll
        for (int i = 0; i < 2; i++)
#pragma unroll
            for (int j = 0; j < NT8; j++)
#pragma unroll
                for (int q = 0; q < 4; q++) acc[i][j][q] = 0.0f;

        auto issueB = [&](int c) {
            const uint4* b = Bt + (size_t)c * BCH;
#pragma unroll
            for (int q = tid; q < BCH; q += TPB)
                cp16(sB_u + (((c & 1) * BCH + q) << 4), b + q);
            CP_COMMIT();
        };

        issueB(0);
        for (int c = 0; c < NCH; c++) {
            if (c + 1 < NCH) { issueB(c + 1); CP_WAIT1(); }
            else             { CP_WAIT0(); }
            __syncthreads();
            const uint4* B = sB4 + (c & 1) * BCH;
#pragma unroll
            for (int kp = 0; kp < 2; kp++) {
                uint4 av0[2], av1[2];
#pragma unroll
                for (int mt = 0; mt < 2; mt++) {
                    av0[mt] = sH2[((c * 4 + 2 * kp) * 8 + wm * 2 + mt) * 32 + lane];
                    av1[mt] = sH2[((c * 4 + 2 * kp + 1) * 8 + wm * 2 + mt) * 32 + lane];
                }
#pragma unroll
                for (int nt = 0; nt < NT8; nt++) {
                    const uint4 bq = B[((wn * NT8 + nt) << 6) + (kp << 5) + lane];
#pragma unroll
                    for (int mt = 0; mt < 2; mt++) {
                        MMA16(acc[mt][nt], av0[mt], bq.x, bq.y);
                        MMA16(acc[mt][nt], av1[mt], bq.z, bq.w);
                    }
                }
            }
            __syncthreads();
        }

        float part[2][2] = {{0.f, 0.f}, {0.f, 0.f}};
        const float* b3v = b3 + t * H3;
        const float* w4v = W4 + t * H3;
#pragma unroll
        for (int nt = 0; nt < NT8; nt++) {
            const int c0 = wn * (H3 / 4) + nt * 8 + 2 * tig;
            const float bb0 = __ldg(b3v + c0), bb1 = __ldg(b3v + c0 + 1);
            const float w0  = __ldg(w4v + c0), w1  = __ldg(w4v + c0 + 1);
#pragma unroll
            for (int mt = 0; mt < 2; mt++) {
                part[mt][0] += celu_f(acc[mt][nt][0] + bb0) * w0
                             + celu_f(acc[mt][nt][1] + bb1) * w1;
                part[mt][1] += celu_f(acc[mt][nt][2] + bb0) * w0
                             + celu_f(acc[mt][nt][3] + bb1) * w1;
            }
        }
#pragma unroll
        for (int mt = 0; mt < 2; mt++)
#pragma unroll
            for (int rh = 0; rh < 2; rh++) {
                part[mt][rh] += __shfl_xor_sync(0xffffffffu, part[mt][rh], 1);
                part[mt][rh] += __shfl_xor_sync(0xffffffffu, part[mt][rh], 2);
            }
        if (tig == 0) {
            const float b4v = __ldg(b4 + t);
#pragma unroll
            for (int mt = 0; mt < 2; mt++)
#pragma unroll
                for (int rh = 0; rh < 2; rh++) {
                    const int row = wm * 32 + mt * 16 + rh * 8 + g;
                    if (row < nact) {
                        const int id = sids[row];
                        const int mol = g_is64 ? batch32[2 * id] : batch32[id];
                        atomicAdd(&out[mol], part[mt][rh] + (wn == 0 ? b4v : 0.0f));
                    }
                }
        }
    }
}

// ---------------- launch ----------------
extern "C" void kernel_launch(void* const* d_in, const int* in_sizes, int n_in,
                              void* d_out, int out_size) {
    const int*   z     = (const int*)  d_in[0];
    const float* feat  = (const float*)d_in[1];
    const int*   batch = (const int*)  d_in[2];
    const float* W1 = (const float*)d_in[4];
    const float* b1 = (const float*)d_in[5];
    const float* W2 = (const float*)d_in[6];
    const float* b2 = (const float*)d_in[7];
    const float* W3 = (const float*)d_in[8];
    const float* b3 = (const float*)d_in[9];
    const float* W4 = (const float*)d_in[10];
    const float* b4 = (const float*)d_in[11];
    float* out = (float*)d_out;

    cudaFuncSetAttribute(k_gemm1,  cudaFuncAttributeMaxDynamicSharedMemorySize, G1_SM_TOTAL);
    cudaFuncSetAttribute(k_gemm23, cudaFuncAttributeMaxDynamicSharedMemorySize, G2_SM_TOTAL);

    const int initN = (out_size > PAD_MAX) ? out_size : PAD_MAX;
    const int prepN = 5 * H1 * KPAD / 4 + 5 * H2 * H1 / 4 + 5 * H3 * H2 / 4;
    const int cpN = (prepN > N_ATOMS) ? prepN : N_ATOMS;

    k_init<<<(initN + 255) / 256, 256>>>(z, out, out_size);            // 1
    dim3 cpg((cpN + 255) / 256, 2);
    k_count_prep<<<cpg, 256>>>(z, W1, W2, W3);                         // 2
    k_scatter<<<(N_ATOMS + 255) / 256, 256>>>();                       // 3

    dim3 grid1(NT_MAX, 2, 5);
    k_gemm1<<<grid1, TPB, G1_SM_TOTAL>>>(feat, b1);                    // 4 <- profiled
    dim3 grid2(NT_MAX, 5);
    k_gemm23<<<grid2, TPB, G2_SM_TOTAL>>>(batch, b2, b3, W4, b4, out); // 5
}

// round 13
// speedup vs baseline: 1.2043x; 1.2043x over previous
#include <cuda_runtime.h>
#include <cuda_fp16.h>
#include <math.h>
#include <stdint.h>

#define N_ATOMS 100000
#define IN_F    1008
#define KPAD    1024
#define H1      256
#define H2      192
#define H3      160
#define CALPHA  0.1f
#define MT      128
#define TPB     512
#define TPB1    256
#define NT_MAX  ((N_ATOMS + MT - 1) / MT)       // 782
#define PAD_MAX ((NT_MAX + 5) * MT)

// ---------------- device scratch (static, no allocations) ----------------
__device__ int g_type[N_ATOMS];
__device__ int g_sorted[PAD_MAX];
__device__ int g_counts[5], g_poff[5], g_cursor[5], g_is64;
// fp16 weights, uint4-fragment order: [t][kc][n8][kp(2)][lane] uint4
__device__ uint2 g_W16_1[5 * H1 * KPAD / 4];
__device__ uint2 g_W16_2[5 * H2 * H1 / 4];
__device__ uint2 g_W16_3[5 * H3 * H2 / 4];
// fp16 fragment-order h1 [tile][ks(16)][bm(8)][lane(32)]
__device__ uint4 g_H1f[(size_t)(NT_MAX + 5) * 16 * 8 * 32];

// ---------------- helpers ----------------
__device__ __forceinline__ float celu_f(float x) {
    return x > 0.0f ? x : CALPHA * expm1f(x * (1.0f / CALPHA));
}
__device__ __forceinline__ uint32_t pack2(float a, float b) {
    __half2 h = __floats2half2_rn(a, b);
    return *reinterpret_cast<uint32_t*>(&h);
}
__device__ __forceinline__ void cp16(uint32_t dst, const void* src) {
    asm volatile("cp.async.cg.shared.global [%0], [%1], 16;"
                 :: "r"(dst), "l"(src) : "memory");
}
__device__ __forceinline__ void cp16z(uint32_t dst, const void* src, int valid) {
    asm volatile("cp.async.cg.shared.global [%0], [%1], 16, %2;"
                 :: "r"(dst), "l"(src), "r"(valid ? 16 : 0) : "memory");
}
#define CP_COMMIT() asm volatile("cp.async.commit_group;" ::: "memory")
#define CP_WAIT0()  asm volatile("cp.async.wait_group 0;" ::: "memory")
#define CP_WAIT1()  asm volatile("cp.async.wait_group 1;" ::: "memory")

#define MMA16(d, a, b0, b1) \
    asm volatile("mma.sync.aligned.m16n8k16.row.col.f32.f16.f16.f32 " \
                 "{%0,%1,%2,%3},{%4,%5,%6,%7},{%8,%9},{%0,%1,%2,%3};" \
                 : "+f"((d)[0]), "+f"((d)[1]), "+f"((d)[2]), "+f"((d)[3]) \
                 : "r"((a).x), "r"((a).y), "r"((a).z), "r"((a).w), \
                   "r"(b0), "r"(b1))

__device__ __forceinline__ uint4 ldsm4(uint32_t addr) {
    uint4 v;
    asm volatile("ldmatrix.sync.aligned.m8n8.x4.shared.b16 {%0,%1,%2,%3}, [%4];"
                 : "=r"(v.x), "=r"(v.y), "=r"(v.z), "=r"(v.w) : "r"(addr));
    return v;
}

// ---------------- plumbing ----------------
__global__ void k_init(const int* __restrict__ z32, float* out, int n_out) {
    int i = blockIdx.x * blockDim.x + threadIdx.x;
    if (i < n_out) out[i] = 0.0f;
    if (i < PAD_MAX) g_sorted[i] = -1;
    if (i == 0) {
        g_is64 = (z32[1] == 0 && z32[3] == 0 && z32[5] == 0 && z32[7] == 0) ? 1 : 0;
        for (int t = 0; t < 5; t++) { g_counts[t] = 0; g_cursor[t] = 0; }
    }
}
__device__ __forceinline__ int z_to_type(int zv) {
    return (zv == 1) ? 0 : (zv == 6) ? 1 : (zv == 7) ? 2 : (zv == 8) ? 3 : 4;
}

// weight permute into uint4-fragment order (KC=64), fp16
template<int KC>
__device__ __forceinline__ void prep_w(uint2* dst, const float* src,
                                       int NN, int KTOT, int KIN, int i) {
    constexpr int KS = KC / 16;
    const int lane = i & 31;
    const int ks   = (i >> 5) % KS;
    int rest = i / (32 * KS);
    const int n8 = rest % (NN / 8); rest /= (NN / 8);
    const int kc = rest % (KTOT / KC);
    const int t  = rest / (KTOT / KC);
    const int n = n8 * 8 + (lane >> 2);
    const int k0 = kc * KC + ks * 16 + 2 * (lane & 3);
    const int k1 = k0 + 8;
    const float* W = src + (size_t)t * KIN * NN;
    float v00 = (k0 < KIN)     ? W[(size_t)k0 * NN + n]       : 0.0f;
    float v01 = (k0 + 1 < KIN) ? W[(size_t)(k0 + 1) * NN + n] : 0.0f;
    float v10 = (k1 < KIN)     ? W[(size_t)k1 * NN + n]       : 0.0f;
    float v11 = (k1 + 1 < KIN) ? W[(size_t)(k1 + 1) * NN + n] : 0.0f;
    const int group = (t * (KTOT / KC) + kc) * (NN / 8) + n8;
    dst[(size_t)group * (KS * 32) + (ks >> 1) * 64 + lane * 2 + (ks & 1)] =
        make_uint2(pack2(v00, v01), pack2(v10, v11));
}

__global__ void k_count_prep(const int* __restrict__ z32,
                             const float* __restrict__ W1,
                             const float* __restrict__ W2,
                             const float* __restrict__ W3) {
    int i = blockIdx.x * blockDim.x + threadIdx.x;
    if (blockIdx.y == 0) {
        if (i >= N_ATOMS) return;
        int zv = g_is64 ? z32[2 * i] : z32[i];
        int t = z_to_type(zv);
        g_type[i] = t;
        atomicAdd(&g_counts[t], 1);
    } else {
        const int n1 = 5 * H1 * KPAD / 4, n2 = 5 * H2 * H1 / 4, n3 = 5 * H3 * H2 / 4;
        if (i < n1) prep_w<64>(g_W16_1, W1, H1, KPAD, IN_F, i);
        else if (i < n1 + n2) prep_w<64>(g_W16_2, W2, H2, H1, H1, i - n1);
        else if (i < n1 + n2 + n3) prep_w<64>(g_W16_3, W3, H3, H2, H2, i - n1 - n2);
    }
}

__global__ void k_scatter() {
    int i = blockIdx.x * blockDim.x + threadIdx.x;
    int off[5]; int acc = 0;
#pragma unroll
    for (int t = 0; t < 5; t++) {
        off[t] = acc;
        acc += ((g_counts[t] + MT - 1) / MT) * MT;
    }
    if (i == 0) {
#pragma unroll
        for (int t = 0; t < 5; t++) g_poff[t] = off[t];
    }
    if (i >= N_ATOMS) return;
    int t = g_type[i];
    int pos = off[t] + atomicAdd(&g_cursor[t], 1);
    g_sorted[pos] = i;
}

// ================= GEMM 1 (N-split, 2 CTAs/SM) =================
// CTA: 128(M) x 128(N) x 1024; 256 threads = 8 warps as 2(M) x 4(N);
// warp tile 64 x 32 (acc 64 regs). grid (NT, 2, 5).
// A32: single buffer 128x64 fp32 (dead after convert -> refill overlaps compute)
// A16: 128 rows x 64 halves, 16B chunk j swizzled j ^ (r&7)
// B:   double buffer 1024 uint4 per stage
#define G1_SM_A32 0                       // 32768 (single)
#define G1_SM_A16 32768                   // 16384
#define G1_SM_B   49152                   // 2*1024 uint4 = 32768
#define G1_SM_IDS 81920                   // 512
#define G1_SM_TOTAL 82432

__global__ void __launch_bounds__(TPB1, 2)
k_gemm1(const float* __restrict__ feat, const float* __restrict__ b1)
{
    constexpr int NCH = KPAD / 64;        // 16
    constexpr int NT8 = 4;                // 4 n8-tiles per warp (32 cols)

    const int t = blockIdx.z;
    const int nh = blockIdx.y;
    const int cnt = g_counts[t];
    const int start = blockIdx.x * MT;
    if (start >= cnt) return;
    const int tile = (g_poff[t] >> 7) + blockIdx.x;

    extern __shared__ __align__(16) char smem[];
    float* sA32 = reinterpret_cast<float*>(smem + G1_SM_A32);
    uint4* sB4  = reinterpret_cast<uint4*>(smem + G1_SM_B);
    int*   sids = reinterpret_cast<int*>(smem + G1_SM_IDS);

    const int tid = threadIdx.x;
    const int wid = tid >> 5, lane = tid & 31;
    const int wm = wid & 1, wn = wid >> 1;
    const int tig = lane & 3;

    if (tid < MT) sids[tid] = g_sorted[tile * MT + tid];
    __syncthreads();

    const uint32_t sA32_u = (uint32_t)__cvta_generic_to_shared(smem + G1_SM_A32);
    const uint32_t sA16_u = (uint32_t)__cvta_generic_to_shared(smem + G1_SM_A16);
    const uint32_t sB_u   = (uint32_t)__cvta_generic_to_shared(sB4);
    const uint4* Bt = reinterpret_cast<const uint4*>(g_W16_1)
                      + (size_t)t * (H1 * KPAD / 8) + nh * 1024;

    const int lrow = wm * 64 + (lane & 15);
    const int ljhi = lane >> 4;
    const int lxor = lrow & 7;

    float acc[4][NT8][4];
#pragma unroll
    for (int i = 0; i < 4; i++)
#pragma unroll
        for (int j = 0; j < NT8; j++)
#pragma unroll
            for (int q = 0; q < 4; q++) acc[i][j][q] = 0.0f;

    auto issueA = [&](int c) {
        // A32 single buffer: 2048 float4, slot jsw = fq ^ (r&15)
#pragma unroll
        for (int q = tid; q < MT * 16; q += TPB1) {
            const int r = q >> 4, fq = q & 15;
            const int id = sids[r];
            const int k = c * 64 + fq * 4;
            const int v = (id >= 0) && (k < IN_F);
            const float* src = feat + (v ? ((size_t)id * IN_F + k) : 0);
            const int jsw = fq ^ (r & 15);
            cp16z(sA32_u + (((r << 6) + (jsw << 2)) << 2), src, v);
        }
    };
    auto issueB = [&](int c) {
        const int s = c & 1;
        const uint4* b = Bt + (size_t)c * 2048;
#pragma unroll
        for (int q = tid; q < 1024; q += TPB1)
            cp16(sB_u + ((s * 1024 + q) << 4), b + q);
    };

    issueA(0); issueB(0); CP_COMMIT();
    for (int c = 0; c < NCH; c++) {
        const int s = c & 1;
        CP_WAIT0();
        __syncthreads();        // A32(c)/B(c) ready; compute(c-1) done (A16 free)

        // convert pass: A32 -> A16 (each thread: 2 slots of 16 floats)
#pragma unroll
        for (int j = 0; j < 2; j++) {
            const int slot = tid + TPB1 * j;
            const int crow = slot & 127;
            const int Q = slot >> 7;
            const float* A32 = sA32 + crow * 64;
            float4 f0 = *reinterpret_cast<const float4*>(A32 + (((4 * Q + 0) ^ (crow & 15)) << 2));
            float4 f1 = *reinterpret_cast<const float4*>(A32 + (((4 * Q + 1) ^ (crow & 15)) << 2));
            float4 f2 = *reinterpret_cast<const float4*>(A32 + (((4 * Q + 2) ^ (crow & 15)) << 2));
            float4 f3 = *reinterpret_cast<const float4*>(A32 + (((4 * Q + 3) ^ (crow & 15)) << 2));
            uint4 v0, v1;
            v0.x = pack2(f0.x, f0.y); v0.y = pack2(f0.z, f0.w);
            v0.z = pack2(f1.x, f1.y); v0.w = pack2(f1.z, f1.w);
            v1.x = pack2(f2.x, f2.y); v1.y = pack2(f2.z, f2.w);
            v1.z = pack2(f3.x, f3.y); v1.w = pack2(f3.z, f3.w);
            const uint32_t d0 = sA16_u + crow * 128 + (((2 * Q) ^ (crow & 7)) << 4);
            const uint32_t d1 = sA16_u + crow * 128 + (((2 * Q + 1) ^ (crow & 7)) << 4);
            asm volatile("st.shared.v4.b32 [%0], {%1,%2,%3,%4};"
                         :: "r"(d0), "r"(v0.x), "r"(v0.y), "r"(v0.z), "r"(v0.w));
            asm volatile("st.shared.v4.b32 [%0], {%1,%2,%3,%4};"
                         :: "r"(d1), "r"(v1.x), "r"(v1.y), "r"(v1.z), "r"(v1.w));
        }
        __syncthreads();        // A16 ready; A32 dead -> refill OK

        if (c + 1 < NCH) { issueA(c + 1); issueB(c + 1); CP_COMMIT(); }

        const uint4* B = sB4 + s * 1024;
#pragma unroll
        for (int kp = 0; kp < 2; kp++) {
            uint4 av0[4], av1[4];
#pragma unroll
            for (int mt = 0; mt < 4; mt++) {
                const int row = lrow + mt * 16;
                const int j0 = ((2 * kp) * 2 + ljhi) ^ lxor;
                const int j1 = ((2 * kp + 1) * 2 + ljhi) ^ lxor;
                av0[mt] = ldsm4(sA16_u + row * 128 + j0 * 16);
                av1[mt] = ldsm4(sA16_u + row * 128 + j1 * 16);
            }
#pragma unroll
            for (int nt = 0; nt < NT8; nt++) {
                const uint4 bq = B[((wn * NT8 + nt) << 6) + (kp << 5) + lane];
#pragma unroll
                for (int mt = 0; mt < 4; mt++) {
                    MMA16(acc[mt][nt], av0[mt], bq.x, bq.y);
                    MMA16(acc[mt][nt], av1[mt], bq.z, bq.w);
                }
            }
        }
    }

    // epilogue: bias+celu -> h1 fragments [ks16][bm8][lane32]
    uint4* Hout = g_H1f + (size_t)tile * 16 * 256;
    const float* bv = b1 + t * H1;
#pragma unroll
    for (int mt = 0; mt < 4; mt++) {
#pragma unroll
        for (int ntp = 0; ntp < NT8 / 2; ntp++) {
            const int nt = 2 * ntp;
            const int c0 = nh * 128 + wn * 32 + nt * 8 + 2 * tig;
            const int c1 = c0 + 8;
            const float bb0 = __ldg(bv + c0), bb1 = __ldg(bv + c0 + 1);
            const float bb2 = __ldg(bv + c1), bb3 = __ldg(bv + c1 + 1);
            uint4 v;
            v.x = pack2(celu_f(acc[mt][nt][0] + bb0),     celu_f(acc[mt][nt][1] + bb1));
            v.y = pack2(celu_f(acc[mt][nt][2] + bb0),     celu_f(acc[mt][nt][3] + bb1));
            v.z = pack2(celu_f(acc[mt][nt + 1][0] + bb2), celu_f(acc[mt][nt + 1][1] + bb3));
            v.w = pack2(celu_f(acc[mt][nt + 1][2] + bb2), celu_f(acc[mt][nt + 1][3] + bb3));
            const int ks = nh * 8 + wn * 2 + ntp;
            const int bm = wm * 4 + mt;
            Hout[(ks * 8 + bm) * 32 + lane] = v;
        }
    }
}

// ================= GEMM 2+3 fused: h1 -> h2 (smem) -> out =================
#define G2_SM_A   0
#define G2_SM_B   32768
#define G2_SM_H2  81920
#define G2_SM_IDS 131072
#define G2_SM_TOTAL 131584

__global__ void __launch_bounds__(TPB)
k_gemm23(const int* __restrict__ batch32,
         const float* __restrict__ b2, const float* __restrict__ b3,
         const float* __restrict__ W4, const float* __restrict__ b4,
         float* __restrict__ out)
{
    const int t = blockIdx.y;
    const int cnt = g_counts[t];
    const int start = blockIdx.x * MT;
    if (start >= cnt) return;
    const int nact = min(MT, cnt - start);
    const int tile = (g_poff[t] >> 7) + blockIdx.x;

    extern __shared__ __align__(16) char smem[];
    uint4* sA   = reinterpret_cast<uint4*>(smem + G2_SM_A);
    uint4* sB4  = reinterpret_cast<uint4*>(smem + G2_SM_B);
    uint4* sH2  = reinterpret_cast<uint4*>(smem + G2_SM_H2);
    int*   sids = reinterpret_cast<int*>(smem + G2_SM_IDS);

    const int tid = threadIdx.x;
    const int wid = tid >> 5, lane = tid & 31;
    const int wm = wid & 3, wn = wid >> 2;
    const int g = lane >> 2, tig = lane & 3;

    if (tid < MT) sids[tid] = g_sorted[tile * MT + tid];
    __syncthreads();

    const uint32_t sA_u = (uint32_t)__cvta_generic_to_shared(sA);
    const uint32_t sB_u = (uint32_t)__cvta_generic_to_shared(sB4);

    // ---------- Layer 2: A = g_H1f, B = g_W16_2, NN=192, K=256 ----------
    {
        constexpr int NCH = 4, NT8 = 6, BCH = H2 * 8;
        const uint4* Asrc = g_H1f + (size_t)tile * 16 * 256;
        const uint4* Bt = reinterpret_cast<const uint4*>(g_W16_2) + (size_t)t * (H2 * H1 / 8);

        float acc[2][NT8][4];
#pragma unroll
        for (int i = 0; i < 2; i++)
#pragma unroll
            for (int j = 0; j < NT8; j++)
#pragma unroll
                for (int q = 0; q < 4; q++) acc[i][j][q] = 0.0f;

        auto issue = [&](int c) {
            const int s = c & 1;
            const uint4* a = Asrc + c * 1024;
#pragma unroll
            for (int q = tid; q < 1024; q += TPB)
                cp16(sA_u + ((s * 1024 + q) << 4), a + q);
            const uint4* b = Bt + (size_t)c * BCH;
#pragma unroll
            for (int q = tid; q < BCH; q += TPB)
                cp16(sB_u + ((s * BCH + q) << 4), b + q);
            CP_COMMIT();
        };

        issue(0);
        for (int c = 0; c < NCH; c++) {
            if (c + 1 < NCH) { issue(c + 1); CP_WAIT1(); }
            else             { CP_WAIT0(); }
            __syncthreads();
            const uint4* A = sA + (c & 1) * 1024;
            const uint4* B = sB4 + (c & 1) * BCH;
#pragma unroll
            for (int kp = 0; kp < 2; kp++) {
                uint4 av0[2], av1[2];
#pragma unroll
                for (int mt = 0; mt < 2; mt++) {
                    av0[mt] = A[((2 * kp) * 8 + wm * 2 + mt) * 32 + lane];
                    av1[mt] = A[((2 * kp + 1) * 8 + wm * 2 + mt) * 32 + lane];
                }
#pragma unroll
                for (int nt = 0; nt < NT8; nt++) {
                    const uint4 bq = B[((wn * NT8 + nt) << 6) + (kp << 5) + lane];
#pragma unroll
                    for (int mt = 0; mt < 2; mt++) {
                        MMA16(acc[mt][nt], av0[mt], bq.x, bq.y);
                        MMA16(acc[mt][nt], av1[mt], bq.z, bq.w);
                    }
                }
            }
            __syncthreads();
        }

        const float* bv = b2 + t * H2;
#pragma unroll
        for (int mt = 0; mt < 2; mt++) {
#pragma unroll
            for (int ntp = 0; ntp < NT8 / 2; ntp++) {
                const int nt = 2 * ntp;
                const int c0 = wn * (H2 / 4) + nt * 8 + 2 * tig;
                const int c1 = c0 + 8;
                const float bb0 = __ldg(bv + c0), bb1 = __ldg(bv + c0 + 1);
                const float bb2 = __ldg(bv + c1), bb3 = __ldg(bv + c1 + 1);
                uint4 v;
                v.x = pack2(celu_f(acc[mt][nt][0] + bb0),     celu_f(acc[mt][nt][1] + bb1));
                v.y = pack2(celu_f(acc[mt][nt][2] + bb0),     celu_f(acc[mt][nt][3] + bb1));
                v.z = pack2(celu_f(acc[mt][nt + 1][0] + bb2), celu_f(acc[mt][nt + 1][1] + bb3));
                v.w = pack2(celu_f(acc[mt][nt + 1][2] + bb2), celu_f(acc[mt][nt + 1][3] + bb3));
                const int ks = wn * (NT8 / 2) + ntp;
                const int bm = wm * 2 + mt;
                sH2[(ks * 8 + bm) * 32 + lane] = v;
            }
        }
    }
    __syncthreads();

    // ---------- Layer 3 + 4: A = sH2, B = g_W16_3, NN=160, K=192 ----------
    {
        constexpr int NCH = 3, NT8 = 5, BCH = H3 * 8;
        const uint4* Bt = reinterpret_cast<const uint4*>(g_W16_3) + (size_t)t * (H3 * H2 / 8);

        float acc[2][NT8][4];
#pragma unroll
        for (int i = 0; i < 2; i++)
#pragma unroll
            for (int j = 0; j < NT8; j++)
#pragma unroll
                for (int q = 0; q < 4; q++) acc[i][j][q] = 0.0f;

        auto issueB = [&](int c) {
            const uint4* b = Bt + (size_t)c * BCH;
#pragma unroll
            for (int q = tid; q < BCH; q += TPB)
                cp16(sB_u + (((c & 1) * BCH + q) << 4), b + q);
            CP_COMMIT();
        };

        issueB(0);
        for (int c = 0; c < NCH; c++) {
            if (c + 1 < NCH) { issueB(c + 1); CP_WAIT1(); }
            else             { CP_WAIT0(); }
            __syncthreads();
            const uint4* B = sB4 + (c & 1) * BCH;
#pragma unroll
            for (int kp = 0; kp < 2; kp++) {
                uint4 av0[2], av1[2];
#pragma unroll
                for (int mt = 0; mt < 2; mt++) {
                    av0[mt] = sH2[((c * 4 + 2 * kp) * 8 + wm * 2 + mt) * 32 + lane];
                    av1[mt] = sH2[((c * 4 + 2 * kp + 1) * 8 + wm * 2 + mt) * 32 + lane];
                }
#pragma unroll
                for (int nt = 0; nt < NT8; nt++) {
                    const uint4 bq = B[((wn * NT8 + nt) << 6) + (kp << 5) + lane];
#pragma unroll
                    for (int mt = 0; mt < 2; mt++) {
                        MMA16(acc[mt][nt], av0[mt], bq.x, bq.y);
                        MMA16(acc[mt][nt], av1[mt], bq.z, bq.w);
                    }
                }
            }
            __syncthreads();
        }

        float part[2][2] = {{0.f, 0.f}, {0.f, 0.f}};
        const float* b3v = b3 + t * H3;
        const float* w4v = W4 + t * H3;
#pragma unroll
        for (int nt = 0; nt < NT8; nt++) {
            const int c0 = wn * (H3 / 4) + nt * 8 + 2 * tig;
            const float bb0 = __ldg(b3v + c0), bb1 = __ldg(b3v + c0 + 1);
            const float w0  = __ldg(w4v + c0), w1  = __ldg(w4v + c0 + 1);
#pragma unroll
            for (int mt = 0; mt < 2; mt++) {
                part[mt][0] += celu_f(acc[mt][nt][0] + bb0) * w0
                             + celu_f(acc[mt][nt][1] + bb1) * w1;
                part[mt][1] += celu_f(acc[mt][nt][2] + bb0) * w0
                             + celu_f(acc[mt][nt][3] + bb1) * w1;
            }
        }
#pragma unroll
        for (int mt = 0; mt < 2; mt++)
#pragma unroll
            for (int rh = 0; rh < 2; rh++) {
                part[mt][rh] += __shfl_xor_sync(0xffffffffu, part[mt][rh], 1);
                part[mt][rh] += __shfl_xor_sync(0xffffffffu, part[mt][rh], 2);
            }
        if (tig == 0) {
            const float b4v = __ldg(b4 + t);
#pragma unroll
            for (int mt = 0; mt < 2; mt++)
#pragma unroll
                for (int rh = 0; rh < 2; rh++) {
                    const int row = wm * 32 + mt * 16 + rh * 8 + g;
                    if (row < nact) {
                        const int id = sids[row];
                        const int mol = g_is64 ? batch32[2 * id] : batch32[id];
                        atomicAdd(&out[mol], part[mt][rh] + (wn == 0 ? b4v : 0.0f));
                    }
                }
        }
    }
}

// ---------------- launch ----------------
extern "C" void kernel_launch(void* const* d_in, const int* in_sizes, int n_in,
                              void* d_out, int out_size) {
    const int*   z     = (const int*)  d_in[0];
    const float* feat  = (const float*)d_in[1];
    const int*   batch = (const int*)  d_in[2];
    const float* W1 = (const float*)d_in[4];
    const float* b1 = (const float*)d_in[5];
    const float* W2 = (const float*)d_in[6];
    const float* b2 = (const float*)d_in[7];
    const float* W3 = (const float*)d_in[8];
    const float* b3 = (const float*)d_in[9];
    const float* W4 = (const float*)d_in[10];
    const float* b4 = (const float*)d_in[11];
    float* out = (float*)d_out;

    cudaFuncSetAttribute(k_gemm1,  cudaFuncAttributeMaxDynamicSharedMemorySize, G1_SM_TOTAL);
    cudaFuncSetAttribute(k_gemm23, cudaFuncAttributeMaxDynamicSharedMemorySize, G2_SM_TOTAL);

    const int initN = (out_size > PAD_MAX) ? out_size : PAD_MAX;
    const int prepN = 5 * H1 * KPAD / 4 + 5 * H2 * H1 / 4 + 5 * H3 * H2 / 4;
    const int cpN = (prepN > N_ATOMS) ? prepN : N_ATOMS;

    k_init<<<(initN + 255) / 256, 256>>>(z, out, out_size);            // 1
    dim3 cpg((cpN + 255) / 256, 2);
    k_count_prep<<<cpg, 256>>>(z, W1, W2, W3);                         // 2
    k_scatter<<<(N_ATOMS + 255) / 256, 256>>>();                       // 3

    dim3 grid1(NT_MAX, 2, 5);
    k_gemm1<<<grid1, TPB1, G1_SM_TOTAL>>>(feat, b1);                   // 4 <- profiled
    dim3 grid2(NT_MAX, 5);
    k_gemm23<<<grid2, TPB, G2_SM_TOTAL>>>(batch, b2, b3, W4, b4, out); // 5
}

// round 14
// speedup vs baseline: 1.2483x; 1.0365x over previous
#include <cuda_runtime.h>
#include <cuda_fp16.h>
#include <math.h>
#include <stdint.h>

#define N_ATOMS 100000
#define IN_F    1008
#define KPAD    1024
#define H1      256
#define H2      192
#define H3      160
#define CALPHA  0.1f
#define MT      128
#define TPB1    256
#define NT_MAX  ((N_ATOMS + MT - 1) / MT)       // 782
#define PAD_MAX ((NT_MAX + 5) * MT)

// ---------------- device scratch (static, no allocations) ----------------
__device__ int g_type[N_ATOMS];
__device__ int g_sorted[PAD_MAX];
__device__ int g_counts[5], g_poff[5], g_cursor[5], g_is64;
// fp16 weights, uint4-pair fragment order (KC=64): per (t,kc,n8) group of 64 uint4,
// inside: kp*32 + lane, uint4 = { ks=2kp:(b0,b1), ks=2kp+1:(b0,b1) }
__device__ uint2 g_W16_1[5 * H1 * KPAD / 4];
__device__ uint2 g_W16_2[5 * H2 * H1 / 4];
__device__ uint2 g_W16_3[5 * H3 * H2 / 4];
// fp16 fragment-order activations [tile][ks][bm(8)][lane(32)]
__device__ uint4 g_H1f[(size_t)(NT_MAX + 5) * 16 * 8 * 32];
__device__ uint4 g_H2f[(size_t)(NT_MAX + 5) * 12 * 8 * 32];

// ---------------- helpers ----------------
__device__ __forceinline__ float celu_f(float x) {
    return x > 0.0f ? x : CALPHA * expm1f(x * (1.0f / CALPHA));
}
__device__ __forceinline__ uint32_t pack2(float a, float b) {
    __half2 h = __floats2half2_rn(a, b);
    return *reinterpret_cast<uint32_t*>(&h);
}
__device__ __forceinline__ void cp16(uint32_t dst, const void* src) {
    asm volatile("cp.async.cg.shared.global [%0], [%1], 16;"
                 :: "r"(dst), "l"(src) : "memory");
}
__device__ __forceinline__ void cp16z(uint32_t dst, const void* src, int valid) {
    asm volatile("cp.async.cg.shared.global [%0], [%1], 16, %2;"
                 :: "r"(dst), "l"(src), "r"(valid ? 16 : 0) : "memory");
}
#define CP_COMMIT() asm volatile("cp.async.commit_group;" ::: "memory")
#define CP_WAIT0()  asm volatile("cp.async.wait_group 0;" ::: "memory")
#define CP_WAIT1()  asm volatile("cp.async.wait_group 1;" ::: "memory")

#define MMA16(d, a, b0, b1) \
    asm volatile("mma.sync.aligned.m16n8k16.row.col.f32.f16.f16.f32 " \
                 "{%0,%1,%2,%3},{%4,%5,%6,%7},{%8,%9},{%0,%1,%2,%3};" \
                 : "+f"((d)[0]), "+f"((d)[1]), "+f"((d)[2]), "+f"((d)[3]) \
                 : "r"((a).x), "r"((a).y), "r"((a).z), "r"((a).w), \
                   "r"(b0), "r"(b1))

__device__ __forceinline__ uint4 ldsm4(uint32_t addr) {
    uint4 v;
    asm volatile("ldmatrix.sync.aligned.m8n8.x4.shared.b16 {%0,%1,%2,%3}, [%4];"
                 : "=r"(v.x), "=r"(v.y), "=r"(v.z), "=r"(v.w) : "r"(addr));
    return v;
}

// ---------------- plumbing ----------------
__global__ void k_init(const int* __restrict__ z32, float* out, int n_out) {
    int i = blockIdx.x * blockDim.x + threadIdx.x;
    if (i < n_out) out[i] = 0.0f;
    if (i < PAD_MAX) g_sorted[i] = -1;
    if (i == 0) {
        g_is64 = (z32[1] == 0 && z32[3] == 0 && z32[5] == 0 && z32[7] == 0) ? 1 : 0;
        for (int t = 0; t < 5; t++) { g_counts[t] = 0; g_cursor[t] = 0; }
    }
}
__device__ __forceinline__ int z_to_type(int zv) {
    return (zv == 1) ? 0 : (zv == 6) ? 1 : (zv == 7) ? 2 : (zv == 8) ? 3 : 4;
}

template<int KC>
__device__ __forceinline__ void prep_w(uint2* dst, const float* src,
                                       int NN, int KTOT, int KIN, int i) {
    constexpr int KS = KC / 16;
    const int lane = i & 31;
    const int ks   = (i >> 5) % KS;
    int rest = i / (32 * KS);
    const int n8 = rest % (NN / 8); rest /= (NN / 8);
    const int kc = rest % (KTOT / KC);
    const int t  = rest / (KTOT / KC);
    const int n = n8 * 8 + (lane >> 2);
    const int k0 = kc * KC + ks * 16 + 2 * (lane & 3);
    const int k1 = k0 + 8;
    const float* W = src + (size_t)t * KIN * NN;
    float v00 = (k0 < KIN)     ? W[(size_t)k0 * NN + n]       : 0.0f;
    float v01 = (k0 + 1 < KIN) ? W[(size_t)(k0 + 1) * NN + n] : 0.0f;
    float v10 = (k1 < KIN)     ? W[(size_t)k1 * NN + n]       : 0.0f;
    float v11 = (k1 + 1 < KIN) ? W[(size_t)(k1 + 1) * NN + n] : 0.0f;
    const int group = (t * (KTOT / KC) + kc) * (NN / 8) + n8;
    dst[(size_t)group * (KS * 32) + (ks >> 1) * 64 + lane * 2 + (ks & 1)] =
        make_uint2(pack2(v00, v01), pack2(v10, v11));
}

__global__ void k_count_prep(const int* __restrict__ z32,
                             const float* __restrict__ W1,
                             const float* __restrict__ W2,
                             const float* __restrict__ W3) {
    int i = blockIdx.x * blockDim.x + threadIdx.x;
    if (blockIdx.y == 0) {
        if (i >= N_ATOMS) return;
        int zv = g_is64 ? z32[2 * i] : z32[i];
        int t = z_to_type(zv);
        g_type[i] = t;
        atomicAdd(&g_counts[t], 1);
    } else {
        const int n1 = 5 * H1 * KPAD / 4, n2 = 5 * H2 * H1 / 4, n3 = 5 * H3 * H2 / 4;
        if (i < n1) prep_w<64>(g_W16_1, W1, H1, KPAD, IN_F, i);
        else if (i < n1 + n2) prep_w<64>(g_W16_2, W2, H2, H1, H1, i - n1);
        else if (i < n1 + n2 + n3) prep_w<64>(g_W16_3, W3, H3, H2, H2, i - n1 - n2);
    }
}

__global__ void k_scatter() {
    int i = blockIdx.x * blockDim.x + threadIdx.x;
    int off[5]; int acc = 0;
#pragma unroll
    for (int t = 0; t < 5; t++) {
        off[t] = acc;
        acc += ((g_counts[t] + MT - 1) / MT) * MT;
    }
    if (i == 0) {
#pragma unroll
        for (int t = 0; t < 5; t++) g_poff[t] = off[t];
    }
    if (i >= N_ATOMS) return;
    int t = g_type[i];
    int pos = off[t] + atomicAdd(&g_cursor[t], 1);
    g_sorted[pos] = i;
}

// ================= GEMM 1 (unchanged R13 winner; N-split, 2 CTAs/SM) =================
#define G1_SM_A32 0                       // 32768 (single)
#define G1_SM_A16 32768                   // 16384
#define G1_SM_B   49152                   // 2*1024 uint4 = 32768
#define G1_SM_IDS 81920                   // 512
#define G1_SM_TOTAL 82432

__global__ void __launch_bounds__(TPB1, 2)
k_gemm1(const float* __restrict__ feat, const float* __restrict__ b1)
{
    constexpr int NCH = KPAD / 64;        // 16
    constexpr int NT8 = 4;

    const int t = blockIdx.z;
    const int nh = blockIdx.y;
    const int cnt = g_counts[t];
    const int start = blockIdx.x * MT;
    if (start >= cnt) return;
    const int tile = (g_poff[t] >> 7) + blockIdx.x;

    extern __shared__ __align__(16) char smem[];
    float* sA32 = reinterpret_cast<float*>(smem + G1_SM_A32);
    uint4* sB4  = reinterpret_cast<uint4*>(smem + G1_SM_B);
    int*   sids = reinterpret_cast<int*>(smem + G1_SM_IDS);

    const int tid = threadIdx.x;
    const int wid = tid >> 5, lane = tid & 31;
    const int wm = wid & 1, wn = wid >> 1;
    const int tig = lane & 3;

    if (tid < MT) sids[tid] = g_sorted[tile * MT + tid];
    __syncthreads();

    const uint32_t sA32_u = (uint32_t)__cvta_generic_to_shared(smem + G1_SM_A32);
    const uint32_t sA16_u = (uint32_t)__cvta_generic_to_shared(smem + G1_SM_A16);
    const uint32_t sB_u   = (uint32_t)__cvta_generic_to_shared(sB4);
    const uint4* Bt = reinterpret_cast<const uint4*>(g_W16_1)
                      + (size_t)t * (H1 * KPAD / 8) + nh * 1024;

    const int lrow = wm * 64 + (lane & 15);
    const int ljhi = lane >> 4;
    const int lxor = lrow & 7;

    float acc[4][NT8][4];
#pragma unroll
    for (int i = 0; i < 4; i++)
#pragma unroll
        for (int j = 0; j < NT8; j++)
#pragma unroll
            for (int q = 0; q < 4; q++) acc[i][j][q] = 0.0f;

    auto issueA = [&](int c) {
#pragma unroll
        for (int q = tid; q < MT * 16; q += TPB1) {
            const int r = q >> 4, fq = q & 15;
            const int id = sids[r];
            const int k = c * 64 + fq * 4;
            const int v = (id >= 0) && (k < IN_F);
            const float* src = feat + (v ? ((size_t)id * IN_F + k) : 0);
            const int jsw = fq ^ (r & 15);
            cp16z(sA32_u + (((r << 6) + (jsw << 2)) << 2), src, v);
        }
    };
    auto issueB = [&](int c) {
        const int s = c & 1;
        const uint4* b = Bt + (size_t)c * 2048;
#pragma unroll
        for (int q = tid; q < 1024; q += TPB1)
            cp16(sB_u + ((s * 1024 + q) << 4), b + q);
    };

    issueA(0); issueB(0); CP_COMMIT();
    for (int c = 0; c < NCH; c++) {
        const int s = c & 1;
        CP_WAIT0();
        __syncthreads();

#pragma unroll
        for (int j = 0; j < 2; j++) {
            const int slot = tid + TPB1 * j;
            const int crow = slot & 127;
            const int Q = slot >> 7;
            const float* A32 = sA32 + crow * 64;
            float4 f0 = *reinterpret_cast<const float4*>(A32 + (((4 * Q + 0) ^ (crow & 15)) << 2));
            float4 f1 = *reinterpret_cast<const float4*>(A32 + (((4 * Q + 1) ^ (crow & 15)) << 2));
            float4 f2 = *reinterpret_cast<const float4*>(A32 + (((4 * Q + 2) ^ (crow & 15)) << 2));
            float4 f3 = *reinterpret_cast<const float4*>(A32 + (((4 * Q + 3) ^ (crow & 15)) << 2));
            uint4 v0, v1;
            v0.x = pack2(f0.x, f0.y); v0.y = pack2(f0.z, f0.w);
            v0.z = pack2(f1.x, f1.y); v0.w = pack2(f1.z, f1.w);
            v1.x = pack2(f2.x, f2.y); v1.y = pack2(f2.z, f2.w);
            v1.z = pack2(f3.x, f3.y); v1.w = pack2(f3.z, f3.w);
            const uint32_t d0 = sA16_u + crow * 128 + (((2 * Q) ^ (crow & 7)) << 4);
            const uint32_t d1 = sA16_u + crow * 128 + (((2 * Q + 1) ^ (crow & 7)) << 4);
            asm volatile("st.shared.v4.b32 [%0], {%1,%2,%3,%4};"
                         :: "r"(d0), "r"(v0.x), "r"(v0.y), "r"(v0.z), "r"(v0.w));
            asm volatile("st.shared.v4.b32 [%0], {%1,%2,%3,%4};"
                         :: "r"(d1), "r"(v1.x), "r"(v1.y), "r"(v1.z), "r"(v1.w));
        }
        __syncthreads();

        if (c + 1 < NCH) { issueA(c + 1); issueB(c + 1); CP_COMMIT(); }

        const uint4* B = sB4 + s * 1024;
#pragma unroll
        for (int kp = 0; kp < 2; kp++) {
            uint4 av0[4], av1[4];
#pragma unroll
            for (int mt = 0; mt < 4; mt++) {
                const int row = lrow + mt * 16;
                const int j0 = ((2 * kp) * 2 + ljhi) ^ lxor;
                const int j1 = ((2 * kp + 1) * 2 + ljhi) ^ lxor;
                av0[mt] = ldsm4(sA16_u + row * 128 + j0 * 16);
                av1[mt] = ldsm4(sA16_u + row * 128 + j1 * 16);
            }
#pragma unroll
            for (int nt = 0; nt < NT8; nt++) {
                const uint4 bq = B[((wn * NT8 + nt) << 6) + (kp << 5) + lane];
#pragma unroll
                for (int mt = 0; mt < 4; mt++) {
                    MMA16(acc[mt][nt], av0[mt], bq.x, bq.y);
                    MMA16(acc[mt][nt], av1[mt], bq.z, bq.w);
                }
            }
        }
    }

    uint4* Hout = g_H1f + (size_t)tile * 16 * 256;
    const float* bv = b1 + t * H1;
#pragma unroll
    for (int mt = 0; mt < 4; mt++) {
#pragma unroll
        for (int ntp = 0; ntp < NT8 / 2; ntp++) {
            const int nt = 2 * ntp;
            const int c0 = nh * 128 + wn * 32 + nt * 8 + 2 * tig;
            const int c1 = c0 + 8;
            const float bb0 = __ldg(bv + c0), bb1 = __ldg(bv + c0 + 1);
            const float bb2 = __ldg(bv + c1), bb3 = __ldg(bv + c1 + 1);
            uint4 v;
            v.x = pack2(celu_f(acc[mt][nt][0] + bb0),     celu_f(acc[mt][nt][1] + bb1));
            v.y = pack2(celu_f(acc[mt][nt][2] + bb0),     celu_f(acc[mt][nt][3] + bb1));
            v.z = pack2(celu_f(acc[mt][nt + 1][0] + bb2), celu_f(acc[mt][nt + 1][1] + bb3));
            v.w = pack2(celu_f(acc[mt][nt + 1][2] + bb2), celu_f(acc[mt][nt + 1][3] + bb3));
            const int ks = nh * 8 + wn * 2 + ntp;
            const int bm = wm * 4 + mt;
            Hout[(ks * 8 + bm) * 32 + lane] = v;
        }
    }
}

// ================= GEMM 2 (N-split, 2 CTAs/SM): h1 -> h2 fragments =================
// CTA: 128 x 96 x 256; 256 threads = 8 warps as 4(M) x 2(N); warp tile 32 x 48.
// grid (NT, 2, 5).
#define G2_SM_A   0                        // 2*1024 uint4 = 32768
#define G2_SM_B   32768                    // 2*768 uint4 = 24576
#define G2_SM_TOTAL 57344

__global__ void __launch_bounds__(TPB1, 2)
k_gemm2(const float* __restrict__ b2)
{
    constexpr int NCH = 4, NT8 = 6, BCH = 768;

    const int t = blockIdx.z;
    const int nh = blockIdx.y;
    const int cnt = g_counts[t];
    const int start = blockIdx.x * MT;
    if (start >= cnt) return;
    const int tile = (g_poff[t] >> 7) + blockIdx.x;

    extern __shared__ __align__(16) char smem[];
    uint4* sA  = reinterpret_cast<uint4*>(smem + G2_SM_A);
    uint4* sB4 = reinterpret_cast<uint4*>(smem + G2_SM_B);

    const int tid = threadIdx.x;
    const int wid = tid >> 5, lane = tid & 31;
    const int wm = wid & 3, wn = wid >> 2;
    const int tig = lane & 3;

    const uint32_t sA_u = (uint32_t)__cvta_generic_to_shared(sA);
    const uint32_t sB_u = (uint32_t)__cvta_generic_to_shared(sB4);
    const uint4* Asrc = g_H1f + (size_t)tile * 16 * 256;
    // W2 groups: (t*4 + kc)*24 + n8; this CTA takes n8 = nh*12 .. nh*12+11
    const uint4* W2u4 = reinterpret_cast<const uint4*>(g_W16_2);

    float acc[2][NT8][4];
#pragma unroll
    for (int i = 0; i < 2; i++)
#pragma unroll
        for (int j = 0; j < NT8; j++)
#pragma unroll
            for (int q = 0; q < 4; q++) acc[i][j][q] = 0.0f;

    auto issue = [&](int c) {
        const int s = c & 1;
        const uint4* a = Asrc + c * 1024;
#pragma unroll
        for (int q = tid; q < 1024; q += TPB1)
            cp16(sA_u + ((s * 1024 + q) << 4), a + q);
        const uint4* b = W2u4 + ((size_t)((t * 4 + c) * 24 + nh * 12)) * 64;
#pragma unroll
        for (int q = tid; q < BCH; q += TPB1)
            cp16(sB_u + ((s * BCH + q) << 4), b + q);
        CP_COMMIT();
    };

    issue(0);
    for (int c = 0; c < NCH; c++) {
        if (c + 1 < NCH) { issue(c + 1); CP_WAIT1(); }
        else             { CP_WAIT0(); }
        __syncthreads();
        const uint4* A = sA + (c & 1) * 1024;
        const uint4* B = sB4 + (c & 1) * BCH;
#pragma unroll
        for (int kp = 0; kp < 2; kp++) {
            uint4 av0[2], av1[2];
#pragma unroll
            for (int mt = 0; mt < 2; mt++) {
                av0[mt] = A[((2 * kp) * 8 + wm * 2 + mt) * 32 + lane];
                av1[mt] = A[((2 * kp + 1) * 8 + wm * 2 + mt) * 32 + lane];
            }
#pragma unroll
            for (int nt = 0; nt < NT8; nt++) {
                const uint4 bq = B[((wn * NT8 + nt) << 6) + (kp << 5) + lane];
#pragma unroll
                for (int mt = 0; mt < 2; mt++) {
                    MMA16(acc[mt][nt], av0[mt], bq.x, bq.y);
                    MMA16(acc[mt][nt], av1[mt], bq.z, bq.w);
                }
            }
        }
        __syncthreads();
    }

    // epilogue: bias+celu -> h2 fragments [ks12][bm8][lane]; CTA owns cols nh*96..+95
    uint4* Hout = g_H2f + (size_t)tile * 12 * 256;
    const float* bv = b2 + t * H2;
#pragma unroll
    for (int mt = 0; mt < 2; mt++) {
#pragma unroll
        for (int ntp = 0; ntp < NT8 / 2; ntp++) {
            const int nt = 2 * ntp;
            const int c0 = nh * 96 + wn * 48 + nt * 8 + 2 * tig;
            const int c1 = c0 + 8;
            const float bb0 = __ldg(bv + c0), bb1 = __ldg(bv + c0 + 1);
            const float bb2 = __ldg(bv + c1), bb3 = __ldg(bv + c1 + 1);
            uint4 v;
            v.x = pack2(celu_f(acc[mt][nt][0] + bb0),     celu_f(acc[mt][nt][1] + bb1));
            v.y = pack2(celu_f(acc[mt][nt][2] + bb0),     celu_f(acc[mt][nt][3] + bb1));
            v.z = pack2(celu_f(acc[mt][nt + 1][0] + bb2), celu_f(acc[mt][nt + 1][1] + bb3));
            v.w = pack2(celu_f(acc[mt][nt + 1][2] + bb2), celu_f(acc[mt][nt + 1][3] + bb3));
            const int ks = nh * 6 + wn * 3 + ntp;
            const int bm = wm * 2 + mt;
            Hout[(ks * 8 + bm) * 32 + lane] = v;
        }
    }
}

// ================= GEMM 3 (2 CTAs/SM): h2 -> layer4 -> segment sum =================
// CTA: 128 x 160 x 192; 256 threads = 8 warps as 4(M) x 2(N); warp tile 32 x 80.
#define G3_SM_A   0                        // 2*1024 uint4 = 32768
#define G3_SM_B   32768                    // 2*1280 uint4 = 40960
#define G3_SM_IDS 73728                    // 512
#define G3_SM_TOTAL 74240

__global__ void __launch_bounds__(TPB1, 2)
k_gemm3(const int* __restrict__ batch32,
        const float* __restrict__ b3, const float* __restrict__ W4,
        const float* __restrict__ b4, float* __restrict__ out)
{
    constexpr int NCH = 3, NT8 = 10, BCH = 1280;

    const int t = blockIdx.y;
    const int cnt = g_counts[t];
    const int start = blockIdx.x * MT;
    if (start >= cnt) return;
    const int nact = min(MT, cnt - start);
    const int tile = (g_poff[t] >> 7) + blockIdx.x;

    extern __shared__ __align__(16) char smem[];
    uint4* sA  = reinterpret_cast<uint4*>(smem + G3_SM_A);
    uint4* sB4 = reinterpret_cast<uint4*>(smem + G3_SM_B);
    int*   sids = reinterpret_cast<int*>(smem + G3_SM_IDS);

    const int tid = threadIdx.x;
    const int wid = tid >> 5, lane = tid & 31;
    const int wm = wid & 3, wn = wid >> 2;
    const int g = lane >> 2, tig = lane & 3;

    if (tid < MT) sids[tid] = g_sorted[tile * MT + tid];
    __syncthreads();

    const uint32_t sA_u = (uint32_t)__cvta_generic_to_shared(sA);
    const uint32_t sB_u = (uint32_t)__cvta_generic_to_shared(sB4);
    const uint4* Asrc = g_H2f + (size_t)tile * 12 * 256;
    const uint4* W3u4 = reinterpret_cast<const uint4*>(g_W16_3);

    float acc[2][NT8][4];
#pragma unroll
    for (int i = 0; i < 2; i++)
#pragma unroll
        for (int j = 0; j < NT8; j++)
#pragma unroll
            for (int q = 0; q < 4; q++) acc[i][j][q] = 0.0f;

    auto issue = [&](int c) {
        const int s = c & 1;
        const uint4* a = Asrc + c * 1024;
#pragma unroll
        for (int q = tid; q < 1024; q += TPB1)
            cp16(sA_u + ((s * 1024 + q) << 4), a + q);
        const uint4* b = W3u4 + ((size_t)(t * 3 + c) * 20) * 64;
#pragma unroll
        for (int q = tid; q < BCH; q += TPB1)
            cp16(sB_u + ((s * BCH + q) << 4), b + q);
        CP_COMMIT();
    };

    issue(0);
    for (int c = 0; c < NCH; c++) {
        if (c + 1 < NCH) { issue(c + 1); CP_WAIT1(); }
        else             { CP_WAIT0(); }
        __syncthreads();
        const uint4* A = sA + (c & 1) * 1024;
        const uint4* B = sB4 + (c & 1) * BCH;
#pragma unroll
        for (int kp = 0; kp < 2; kp++) {
            uint4 av0[2], av1[2];
#pragma unroll
            for (int mt = 0; mt < 2; mt++) {
                av0[mt] = A[((2 * kp) * 8 + wm * 2 + mt) * 32 + lane];
                av1[mt] = A[((2 * kp + 1) * 8 + wm * 2 + mt) * 32 + lane];
            }
#pragma unroll
            for (int nt = 0; nt < NT8; nt++) {
                const uint4 bq = B[((wn * NT8 + nt) << 6) + (kp << 5) + lane];
#pragma unroll
                for (int mt = 0; mt < 2; mt++) {
                    MMA16(acc[mt][nt], av0[mt], bq.x, bq.y);
                    MMA16(acc[mt][nt], av1[mt], bq.z, bq.w);
                }
            }
        }
        __syncthreads();
    }

    // epilogue 3 + layer 4 + segment sum
    float part[2][2] = {{0.f, 0.f}, {0.f, 0.f}};
    const float* b3v = b3 + t * H3;
    const float* w4v = W4 + t * H3;
#pragma unroll
    for (int nt = 0; nt < NT8; nt++) {
        const int c0 = wn * 80 + nt * 8 + 2 * tig;
        const float bb0 = __ldg(b3v + c0), bb1 = __ldg(b3v + c0 + 1);
        const float w0  = __ldg(w4v + c0), w1  = __ldg(w4v + c0 + 1);
#pragma unroll
        for (int mt = 0; mt < 2; mt++) {
            part[mt][0] += celu_f(acc[mt][nt][0] + bb0) * w0
                         + celu_f(acc[mt][nt][1] + bb1) * w1;
            part[mt][1] += celu_f(acc[mt][nt][2] + bb0) * w0
                         + celu_f(acc[mt][nt][3] + bb1) * w1;
        }
    }
#pragma unroll
    for (int mt = 0; mt < 2; mt++)
#pragma unroll
        for (int rh = 0; rh < 2; rh++) {
            part[mt][rh] += __shfl_xor_sync(0xffffffffu, part[mt][rh], 1);
            part[mt][rh] += __shfl_xor_sync(0xffffffffu, part[mt][rh], 2);
        }
    if (tig == 0) {
        const float b4v = __ldg(b4 + t);
#pragma unroll
        for (int mt = 0; mt < 2; mt++)
#pragma unroll
            for (int rh = 0; rh < 2; rh++) {
                const int row = wm * 32 + mt * 16 + rh * 8 + g;
                if (row < nact) {
                    const int id = sids[row];
                    const int mol = g_is64 ? batch32[2 * id] : batch32[id];
                    atomicAdd(&out[mol], part[mt][rh] + (wn == 0 ? b4v : 0.0f));
                }
            }
    }
}

// ---------------- launch ----------------
extern "C" void kernel_launch(void* const* d_in, const int* in_sizes, int n_in,
                              void* d_out, int out_size) {
    const int*   z     = (const int*)  d_in[0];
    const float* feat  = (const float*)d_in[1];
    const int*   batch = (const int*)  d_in[2];
    const float* W1 = (const float*)d_in[4];
    const float* b1 = (const float*)d_in[5];
    const float* W2 = (const float*)d_in[6];
    const float* b2 = (const float*)d_in[7];
    const float* W3 = (const float*)d_in[8];
    const float* b3 = (const float*)d_in[9];
    const float* W4 = (const float*)d_in[10];
    const float* b4 = (const float*)d_in[11];
    float* out = (float*)d_out;

    cudaFuncSetAttribute(k_gemm1, cudaFuncAttributeMaxDynamicSharedMemorySize, G1_SM_TOTAL);
    cudaFuncSetAttribute(k_gemm2, cudaFuncAttributeMaxDynamicSharedMemorySize, G2_SM_TOTAL);
    cudaFuncSetAttribute(k_gemm3, cudaFuncAttributeMaxDynamicSharedMemorySize, G3_SM_TOTAL);

    const int initN = (out_size > PAD_MAX) ? out_size : PAD_MAX;
    const int prepN = 5 * H1 * KPAD / 4 + 5 * H2 * H1 / 4 + 5 * H3 * H2 / 4;
    const int cpN = (prepN > N_ATOMS) ? prepN : N_ATOMS;

    k_init<<<(initN + 255) / 256, 256>>>(z, out, out_size);            // 1
    dim3 cpg((cpN + 255) / 256, 2);
    k_count_prep<<<cpg, 256>>>(z, W1, W2, W3);                         // 2
    k_scatter<<<(N_ATOMS + 255) / 256, 256>>>();                       // 3

    dim3 grid1(NT_MAX, 2, 5);
    k_gemm1<<<grid1, TPB1, G1_SM_TOTAL>>>(feat, b1);                   // 4 <- profiled
    dim3 grid2(NT_MAX, 2, 5);
    k_gemm2<<<grid2, TPB1, G2_SM_TOTAL>>>(b2);                         // 5
    dim3 grid3(NT_MAX, 5);
    k_gemm3<<<grid3, TPB1, G3_SM_TOTAL>>>(batch, b3, W4, b4, out);     // 6
}

// round 16
// speedup vs baseline: 1.3925x; 1.1156x over previous
#include <cuda_runtime.h>
#include <cuda_fp16.h>
#include <math.h>
#include <stdint.h>

#define N_ATOMS 100000
#define IN_F    1008
#define KPAD    1024
#define H1      256
#define H2      192
#define H3      160
#define CALPHA  0.1f
#define MT      128
#define TPB1    256
#define NT_MAX  ((N_ATOMS + MT - 1) / MT)       // 782
#define PAD_MAX ((NT_MAX + 5) * MT)

// ---------------- device scratch (static, no allocations) ----------------
__device__ int g_type[N_ATOMS];
__device__ int g_sorted[PAD_MAX];
__device__ int g_counts[5], g_poff[5], g_cursor[5], g_is64;
__device__ uint2 g_W16_1[5 * H1 * KPAD / 4];
__device__ uint2 g_W16_2[5 * H2 * H1 / 4];
__device__ uint2 g_W16_3[5 * H3 * H2 / 4];
__device__ uint4 g_H1f[(size_t)(NT_MAX + 5) * 16 * 8 * 32];
__device__ uint4 g_H2f[(size_t)(NT_MAX + 5) * 12 * 8 * 32];

// ---------------- helpers ----------------
__device__ __forceinline__ float celu_f(float x) {
    return x > 0.0f ? x : CALPHA * expm1f(x * (1.0f / CALPHA));
}
__device__ __forceinline__ uint32_t pack2(float a, float b) {
    __half2 h = __floats2half2_rn(a, b);
    return *reinterpret_cast<uint32_t*>(&h);
}
__device__ __forceinline__ void cp16(uint32_t dst, const void* src) {
    asm volatile("cp.async.cg.shared.global [%0], [%1], 16;"
                 :: "r"(dst), "l"(src) : "memory");
}
__device__ __forceinline__ void cp16z(uint32_t dst, const void* src, int valid) {
    asm volatile("cp.async.cg.shared.global [%0], [%1], 16, %2;"
                 :: "r"(dst), "l"(src), "r"(valid ? 16 : 0) : "memory");
}
#define CP_COMMIT() asm volatile("cp.async.commit_group;" ::: "memory")
#define CP_WAIT0()  asm volatile("cp.async.wait_group 0;" ::: "memory")
#define CP_WAIT1()  asm volatile("cp.async.wait_group 1;" ::: "memory")

#define MMA16(d, a, b0, b1) \
    asm volatile("mma.sync.aligned.m16n8k16.row.col.f32.f16.f16.f32 " \
                 "{%0,%1,%2,%3},{%4,%5,%6,%7},{%8,%9},{%0,%1,%2,%3};" \
                 : "+f"((d)[0]), "+f"((d)[1]), "+f"((d)[2]), "+f"((d)[3]) \
                 : "r"((a).x), "r"((a).y), "r"((a).z), "r"((a).w), \
                   "r"(b0), "r"(b1))

__device__ __forceinline__ uint4 ldsm4(uint32_t addr) {
    uint4 v;
    asm volatile("ldmatrix.sync.aligned.m8n8.x4.shared.b16 {%0,%1,%2,%3}, [%4];"
                 : "=r"(v.x), "=r"(v.y), "=r"(v.z), "=r"(v.w) : "r"(addr));
    return v;
}

// ---------------- plumbing ----------------
__global__ void k_init(const int* __restrict__ z32, float* out, int n_out) {
    int i = blockIdx.x * blockDim.x + threadIdx.x;
    if (i < n_out) out[i] = 0.0f;
    if (i < PAD_MAX) g_sorted[i] = -1;
    if (i == 0) {
        g_is64 = (z32[1] == 0 && z32[3] == 0 && z32[5] == 0 && z32[7] == 0) ? 1 : 0;
        for (int t = 0; t < 5; t++) { g_counts[t] = 0; g_cursor[t] = 0; }
    }
}
__device__ __forceinline__ int z_to_type(int zv) {
    return (zv == 1) ? 0 : (zv == 6) ? 1 : (zv == 7) ? 2 : (zv == 8) ? 3 : 4;
}

template<int KC>
__device__ __forceinline__ void prep_w(uint2* dst, const float* src,
                                       int NN, int KTOT, int KIN, int i) {
    constexpr int KS = KC / 16;
    const int lane = i & 31;
    const int ks   = (i >> 5) % KS;
    int rest = i / (32 * KS);
    const int n8 = rest % (NN / 8); rest /= (NN / 8);
    const int kc = rest % (KTOT / KC);
    const int t  = rest / (KTOT / KC);
    const int n = n8 * 8 + (lane >> 2);
    const int k0 = kc * KC + ks * 16 + 2 * (lane & 3);
    const int k1 = k0 + 8;
    const float* W = src + (size_t)t * KIN * NN;
    float v00 = (k0 < KIN)     ? W[(size_t)k0 * NN + n]       : 0.0f;
    float v01 = (k0 + 1 < KIN) ? W[(size_t)(k0 + 1) * NN + n] : 0.0f;
    float v10 = (k1 < KIN)     ? W[(size_t)k1 * NN + n]       : 0.0f;
    float v11 = (k1 + 1 < KIN) ? W[(size_t)(k1 + 1) * NN + n] : 0.0f;
    const int group = (t * (KTOT / KC) + kc) * (NN / 8) + n8;
    dst[(size_t)group * (KS * 32) + (ks >> 1) * 64 + lane * 2 + (ks & 1)] =
        make_uint2(pack2(v00, v01), pack2(v10, v11));
}

__global__ void k_count_prep(const int* __restrict__ z32,
                             const float* __restrict__ W1,
                             const float* __restrict__ W2,
                             const float* __restrict__ W3) {
    int i = blockIdx.x * blockDim.x + threadIdx.x;
    if (blockIdx.y == 0) {
        __shared__ int s_cnt[5];
        if (threadIdx.x < 5) s_cnt[threadIdx.x] = 0;
        __syncthreads();
        if (i < N_ATOMS) {
            int zv = g_is64 ? z32[2 * i] : z32[i];
            int t = z_to_type(zv);
            g_type[i] = t;
            atomicAdd(&s_cnt[t], 1);
        }
        __syncthreads();
        if (threadIdx.x < 5 && s_cnt[threadIdx.x] > 0)
            atomicAdd(&g_counts[threadIdx.x], s_cnt[threadIdx.x]);
    } else {
        const int n1 = 5 * H1 * KPAD / 4, n2 = 5 * H2 * H1 / 4, n3 = 5 * H3 * H2 / 4;
        if (i < n1) prep_w<64>(g_W16_1, W1, H1, KPAD, IN_F, i);
        else if (i < n1 + n2) prep_w<64>(g_W16_2, W2, H2, H1, H1, i - n1);
        else if (i < n1 + n2 + n3) prep_w<64>(g_W16_3, W3, H3, H2, H2, i - n1 - n2);
    }
}

// CTA-aggregated scatter (one global atomic per type per block)
__global__ void k_scatter() {
    __shared__ int s_cnt[5], s_base[5];
    const int i = blockIdx.x * blockDim.x + threadIdx.x;
    if (threadIdx.x < 5) s_cnt[threadIdx.x] = 0;
    __syncthreads();
    int t = -1, pos = 0;
    if (i < N_ATOMS) {
        t = g_type[i];
        pos = atomicAdd(&s_cnt[t], 1);
    }
    __syncthreads();
    if (threadIdx.x < 5) {
        int off = 0;
#pragma unroll
        for (int u = 0; u < 5; u++) {
            if (u == threadIdx.x) break;
            off += ((g_counts[u] + MT - 1) / MT) * MT;
        }
        g_poff[threadIdx.x] = off;   // same value from every block: benign
        s_base[threadIdx.x] = off +
            (s_cnt[threadIdx.x] > 0 ? atomicAdd(&g_cursor[threadIdx.x], s_cnt[threadIdx.x]) : 0);
    }
    __syncthreads();
    if (i < N_ATOMS) g_sorted[s_base[t] + pos] = i;
}

// ================= GEMM 1 (N-split, nh fastest grid dim, 2 CTAs/SM) =================
#define G1_SM_A32 0                       // 32768 (single)
#define G1_SM_A16 32768                   // 16384
#define G1_SM_B   49152                   // 2*1024 uint4 = 32768
#define G1_SM_IDS 81920                   // 512
#define G1_SM_TOTAL 82432

__global__ void __launch_bounds__(TPB1, 2)
k_gemm1(const float* __restrict__ feat, const float* __restrict__ b1)
{
    constexpr int NCH = KPAD / 64;        // 16
    constexpr int NT8 = 4;

    const int t = blockIdx.z;
    const int nh = blockIdx.x;            // fastest dim -> nh pairs adjacent (L2 share)
    const int cnt = g_counts[t];
    const int start = blockIdx.y * MT;
    if (start >= cnt) return;
    const int tile = (g_poff[t] >> 7) + blockIdx.y;

    extern __shared__ __align__(16) char smem[];
    float* sA32 = reinterpret_cast<float*>(smem + G1_SM_A32);
    uint4* sB4  = reinterpret_cast<uint4*>(smem + G1_SM_B);
    int*   sids = reinterpret_cast<int*>(smem + G1_SM_IDS);

    const int tid = threadIdx.x;
    const int wid = tid >> 5, lane = tid & 31;
    const int wm = wid & 1, wn = wid >> 1;
    const int tig = lane & 3;

    if (tid < MT) sids[tid] = g_sorted[tile * MT + tid];
    __syncthreads();

    const uint32_t sA32_u = (uint32_t)__cvta_generic_to_shared(smem + G1_SM_A32);
    const uint32_t sA16_u = (uint32_t)__cvta_generic_to_shared(smem + G1_SM_A16);
    const uint32_t sB_u   = (uint32_t)__cvta_generic_to_shared(sB4);
    const uint4* Bt = reinterpret_cast<const uint4*>(g_W16_1)
                      + (size_t)t * (H1 * KPAD / 8) + nh * 1024;

    const int lrow = wm * 64 + (lane & 15);
    const int ljhi = lane >> 4;
    const int lxor = lrow & 7;

    // hoisted issueA constants: thread covers q = tid + 256*j, j<8
    //   -> row r = (tid>>4) + 16*j, fq = tid&15 (r&15 invariant across j)
    const int a_fq = tid & 15;
    const int a_r0 = tid >> 4;
    const uint32_t a_dst0 = sA32_u + (((a_r0 << 6) + ((a_fq ^ (a_r0 & 15)) << 2)) << 2);

    float acc[4][NT8][4];
#pragma unroll
    for (int i = 0; i < 4; i++)
#pragma unroll
        for (int j = 0; j < NT8; j++)
#pragma unroll
            for (int q = 0; q < 4; q++) acc[i][j][q] = 0.0f;

    auto issueA = [&](int c) {
        const int k = c * 64 + a_fq * 4;
        const int kv = (k < IN_F);
#pragma unroll
        for (int j = 0; j < 8; j++) {               // 8 iterations: rows 0..127
            const int id = sids[a_r0 + 16 * j];
            const int v = (id >= 0) && kv;
            const float* src = feat + (v ? ((size_t)id * IN_F + k) : 0);
            cp16z(a_dst0 + j * 4096, src, v);
        }
    };
    auto issueB = [&](int c) {
        const int s = c & 1;
        const uint4* b = Bt + (size_t)c * 2048;
#pragma unroll
        for (int q = tid; q < 1024; q += TPB1)
            cp16(sB_u + ((s * 1024 + q) << 4), b + q);
    };

    issueA(0); issueB(0); CP_COMMIT();
    for (int c = 0; c < NCH; c++) {
        const int s = c & 1;
        CP_WAIT0();
        __syncthreads();

#pragma unroll
        for (int j = 0; j < 2; j++) {
            const int slot = tid + TPB1 * j;
            const int crow = slot & 127;
            const int Q = slot >> 7;
            const float* A32 = sA32 + crow * 64;
            float4 f0 = *reinterpret_cast<const float4*>(A32 + (((4 * Q + 0) ^ (crow & 15)) << 2));
            float4 f1 = *reinterpret_cast<const float4*>(A32 + (((4 * Q + 1) ^ (crow & 15)) << 2));
            float4 f2 = *reinterpret_cast<const float4*>(A32 + (((4 * Q + 2) ^ (crow & 15)) << 2));
            float4 f3 = *reinterpret_cast<const float4*>(A32 + (((4 * Q + 3) ^ (crow & 15)) << 2));
            uint4 v0, v1;
            v0.x = pack2(f0.x, f0.y); v0.y = pack2(f0.z, f0.w);
            v0.z = pack2(f1.x, f1.y); v0.w = pack2(f1.z, f1.w);
            v1.x = pack2(f2.x, f2.y); v1.y = pack2(f2.z, f2.w);
            v1.z = pack2(f3.x, f3.y); v1.w = pack2(f3.z, f3.w);
            const uint32_t d0 = sA16_u + crow * 128 + (((2 * Q) ^ (crow & 7)) << 4);
            const uint32_t d1 = sA16_u + crow * 128 + (((2 * Q + 1) ^ (crow & 7)) << 4);
            asm volatile("st.shared.v4.b32 [%0], {%1,%2,%3,%4};"
                         :: "r"(d0), "r"(v0.x), "r"(v0.y), "r"(v0.z), "r"(v0.w));
            asm volatile("st.shared.v4.b32 [%0], {%1,%2,%3,%4};"
                         :: "r"(d1), "r"(v1.x), "r"(v1.y), "r"(v1.z), "r"(v1.w));
        }
        __syncthreads();

        if (c + 1 < NCH) { issueA(c + 1); issueB(c + 1); CP_COMMIT(); }

        const uint4* B = sB4 + s * 1024;
#pragma unroll
        for (int kp = 0; kp < 2; kp++) {
            uint4 av0[4], av1[4];
#pragma unroll
            for (int mt = 0; mt < 4; mt++) {
                const int row = lrow + mt * 16;
                const int j0 = ((2 * kp) * 2 + ljhi) ^ lxor;
                const int j1 = ((2 * kp + 1) * 2 + ljhi) ^ lxor;
                av0[mt] = ldsm4(sA16_u + row * 128 + j0 * 16);
                av1[mt] = ldsm4(sA16_u + row * 128 + j1 * 16);
            }
#pragma unroll
            for (int nt = 0; nt < NT8; nt++) {
                const uint4 bq = B[((wn * NT8 + nt) << 6) + (kp << 5) + lane];
#pragma unroll
                for (int mt = 0; mt < 4; mt++) {
                    MMA16(acc[mt][nt], av0[mt], bq.x, bq.y);
                    MMA16(acc[mt][nt], av1[mt], bq.z, bq.w);
                }
            }
        }
    }

    uint4* Hout = g_H1f + (size_t)tile * 16 * 256;
    const float* bv = b1 + t * H1;
#pragma unroll
    for (int mt = 0; mt < 4; mt++) {
#pragma unroll
        for (int ntp = 0; ntp < NT8 / 2; ntp++) {
            const int nt = 2 * ntp;
            const int c0 = nh * 128 + wn * 32 + nt * 8 + 2 * tig;
            const int c1 = c0 + 8;
            const float bb0 = __ldg(bv + c0), bb1 = __ldg(bv + c0 + 1);
            const float bb2 = __ldg(bv + c1), bb3 = __ldg(bv + c1 + 1);
            uint4 v;
            v.x = pack2(celu_f(acc[mt][nt][0] + bb0),     celu_f(acc[mt][nt][1] + bb1));
            v.y = pack2(celu_f(acc[mt][nt][2] + bb0),     celu_f(acc[mt][nt][3] + bb1));
            v.z = pack2(celu_f(acc[mt][nt + 1][0] + bb2), celu_f(acc[mt][nt + 1][1] + bb3));
            v.w = pack2(celu_f(acc[mt][nt + 1][2] + bb2), celu_f(acc[mt][nt + 1][3] + bb3));
            const int ks = nh * 8 + wn * 2 + ntp;
            const int bm = wm * 4 + mt;
            Hout[(ks * 8 + bm) * 32 + lane] = v;
        }
    }
}

// ================= GEMM 2 (N-split, nh fastest, 2 CTAs/SM) =================
#define G2_SM_A   0                        // 2*1024 uint4 = 32768
#define G2_SM_B   32768                    // 2*768 uint4 = 24576
#define G2_SM_TOTAL 57344

__global__ void __launch_bounds__(TPB1, 2)
k_gemm2(const float* __restrict__ b2)
{
    constexpr int NCH = 4, NT8 = 6, BCH = 768;

    const int t = blockIdx.z;
    const int nh = blockIdx.x;
    const int cnt = g_counts[t];
    const int start = blockIdx.y * MT;
    if (start >= cnt) return;
    const int tile = (g_poff[t] >> 7) + blockIdx.y;

    extern __shared__ __align__(16) char smem[];
    uint4* sA  = reinterpret_cast<uint4*>(smem + G2_SM_A);
    uint4* sB4 = reinterpret_cast<uint4*>(smem + G2_SM_B);

    const int tid = threadIdx.x;
    const int wid = tid >> 5, lane = tid & 31;
    const int wm = wid & 3, wn = wid >> 2;
    const int tig = lane & 3;

    const uint32_t sA_u = (uint32_t)__cvta_generic_to_shared(sA);
    const uint32_t sB_u = (uint32_t)__cvta_generic_to_shared(sB4);
    const uint4* Asrc = g_H1f + (size_t)tile * 16 * 256;
    const uint4* W2u4 = reinterpret_cast<const uint4*>(g_W16_2);

    float acc[2][NT8][4];
#pragma unroll
    for (int i = 0; i < 2; i++)
#pragma unroll
        for (int j = 0; j < NT8; j++)
#pragma unroll
            for (int q = 0; q < 4; q++) acc[i][j][q] = 0.0f;

    auto issue = [&](int c) {
        const int s = c & 1;
        const uint4* a = Asrc + c * 1024;
#pragma unroll
        for (int q = tid; q < 1024; q += TPB1)
            cp16(sA_u + ((s * 1024 + q) << 4), a + q);
        const uint4* b = W2u4 + ((size_t)((t * 4 + c) * 24 + nh * 12)) * 64;
#pragma unroll
        for (int q = tid; q < BCH; q += TPB1)
            cp16(sB_u + ((s * BCH + q) << 4), b + q);
        CP_COMMIT();
    };

    issue(0);
    for (int c = 0; c < NCH; c++) {
        if (c + 1 < NCH) { issue(c + 1); CP_WAIT1(); }
        else             { CP_WAIT0(); }
        __syncthreads();
        const uint4* A = sA + (c & 1) * 1024;
        const uint4* B = sB4 + (c & 1) * BCH;
#pragma unroll
        for (int kp = 0; kp < 2; kp++) {
            uint4 av0[2], av1[2];
#pragma unroll
            for (int mt = 0; mt < 2; mt++) {
                av0[mt] = A[((2 * kp) * 8 + wm * 2 + mt) * 32 + lane];
                av1[mt] = A[((2 * kp + 1) * 8 + wm * 2 + mt) * 32 + lane];
            }
#pragma unroll
            for (int nt = 0; nt < NT8; nt++) {
                const uint4 bq = B[((wn * NT8 + nt) << 6) + (kp << 5) + lane];
#pragma unroll
                for (int mt = 0; mt < 2; mt++) {
                    MMA16(acc[mt][nt], av0[mt], bq.x, bq.y);
                    MMA16(acc[mt][nt], av1[mt], bq.z, bq.w);
                }
            }
        }
        __syncthreads();
    }

    uint4* Hout = g_H2f + (size_t)tile * 12 * 256;
    const float* bv = b2 + t * H2;
#pragma unroll
    for (int mt = 0; mt < 2; mt++) {
#pragma unroll
        for (int ntp = 0; ntp < NT8 / 2; ntp++) {
            const int nt = 2 * ntp;
            const int c0 = nh * 96 + wn * 48 + nt * 8 + 2 * tig;
            const int c1 = c0 + 8;
            const float bb0 = __ldg(bv + c0), bb1 = __ldg(bv + c0 + 1);
            const float bb2 = __ldg(bv + c1), bb3 = __ldg(bv + c1 + 1);
            uint4 v;
            v.x = pack2(celu_f(acc[mt][nt][0] + bb0),     celu_f(acc[mt][nt][1] + bb1));
            v.y = pack2(celu_f(acc[mt][nt][2] + bb0),     celu_f(acc[mt][nt][3] + bb1));
            v.z = pack2(celu_f(acc[mt][nt + 1][0] + bb2), celu_f(acc[mt][nt + 1][1] + bb3));
            v.w = pack2(celu_f(acc[mt][nt + 1][2] + bb2), celu_f(acc[mt][nt + 1][3] + bb3));
            const int ks = nh * 6 + wn * 3 + ntp;
            const int bm = wm * 2 + mt;
            Hout[(ks * 8 + bm) * 32 + lane] = v;
        }
    }
}

// ================= GEMM 3 (2 CTAs/SM): h2 -> layer4 -> segment sum =================
#define G3_SM_A   0                        // 2*1024 uint4 = 32768
#define G3_SM_B   32768                    // 2*1280 uint4 = 40960
#define G3_SM_IDS 73728                    // 512
#define G3_SM_TOTAL 74240

__global__ void __launch_bounds__(TPB1, 2)
k_gemm3(const int* __restrict__ batch32,
        const float* __restrict__ b3, const float* __restrict__ W4,
        const float* __restrict__ b4, float* __restrict__ out)
{
    constexpr int NCH = 3, NT8 = 10, BCH = 1280;

    const int t = blockIdx.y;
    const int cnt = g_counts[t];
    const int start = blockIdx.x * MT;
    if (start >= cnt) return;
    const int nact = min(MT, cnt - start);
    const int tile = (g_poff[t] >> 7) + blockIdx.x;

    extern __shared__ __align__(16) char smem[];
    uint4* sA  = reinterpret_cast<uint4*>(smem + G3_SM_A);
    uint4* sB4 = reinterpret_cast<uint4*>(smem + G3_SM_B);
    int*   sids = reinterpret_cast<int*>(smem + G3_SM_IDS);

    const int tid = threadIdx.x;
    const int wid = tid >> 5, lane = tid & 31;
    const int wm = wid & 3, wn = wid >> 2;
    const int g = lane >> 2, tig = lane & 3;

    if (tid < MT) sids[tid] = g_sorted[tile * MT + tid];
    __syncthreads();

    const uint32_t sA_u = (uint32_t)__cvta_generic_to_shared(sA);
    const uint32_t sB_u = (uint32_t)__cvta_generic_to_shared(sB4);
    const uint4* Asrc = g_H2f + (size_t)tile * 12 * 256;
    const uint4* W3u4 = reinterpret_cast<const uint4*>(g_W16_3);

    float acc[2][NT8][4];
#pragma unroll
    for (int i = 0; i < 2; i++)
#pragma unroll
        for (int j = 0; j < NT8; j++)
#pragma unroll
            for (int q = 0; q < 4; q++) acc[i][j][q] = 0.0f;

    auto issue = [&](int c) {
        const int s = c & 1;
        const uint4* a = Asrc + c * 1024;
#pragma unroll
        for (int q = tid; q < 1024; q += TPB1)
            cp16(sA_u + ((s * 1024 + q) << 4), a + q);
        const uint4* b = W3u4 + ((size_t)(t * 3 + c) * 20) * 64;
#pragma unroll
        for (int q = tid; q < BCH; q += TPB1)
            cp16(sB_u + ((s * BCH + q) << 4), b + q);
        CP_COMMIT();
    };

    issue(0);
    for (int c = 0; c < NCH; c++) {
        if (c + 1 < NCH) { issue(c + 1); CP_WAIT1(); }
        else             { CP_WAIT0(); }
        __syncthreads();
        const uint4* A = sA + (c & 1) * 1024;
        const uint4* B = sB4 + (c & 1) * BCH;
#pragma unroll
        for (int kp = 0; kp < 2; kp++) {
            uint4 av0[2], av1[2];
#pragma unroll
            for (int mt = 0; mt < 2; mt++) {
                av0[mt] = A[((2 * kp) * 8 + wm * 2 + mt) * 32 + lane];
                av1[mt] = A[((2 * kp + 1) * 8 + wm * 2 + mt) * 32 + lane];
            }
#pragma unroll
            for (int nt = 0; nt < NT8; nt++) {
                const uint4 bq = B[((wn * NT8 + nt) << 6) + (kp << 5) + lane];
#pragma unroll
                for (int mt = 0; mt < 2; mt++) {
                    MMA16(acc[mt][nt], av0[mt], bq.x, bq.y);
                    MMA16(acc[mt][nt], av1[mt], bq.z, bq.w);
                }
            }
        }
        __syncthreads();
    }

    float part[2][2] = {{0.f, 0.f}, {0.f, 0.f}};
    const float* b3v = b3 + t * H3;
    const float* w4v = W4 + t * H3;
#pragma unroll
    for (int nt = 0; nt < NT8; nt++) {
        const int c0 = wn * 80 + nt * 8 + 2 * tig;
        const float bb0 = __ldg(b3v + c0), bb1 = __ldg(b3v + c0 + 1);
        const float w0  = __ldg(w4v + c0), w1  = __ldg(w4v + c0 + 1);
#pragma unroll
        for (int mt = 0; mt < 2; mt++) {
            part[mt][0] += celu_f(acc[mt][nt][0] + bb0) * w0
                         + celu_f(acc[mt][nt][1] + bb1) * w1;
            part[mt][1] += celu_f(acc[mt][nt][2] + bb0) * w0
                         + celu_f(acc[mt][nt][3] + bb1) * w1;
        }
    }
#pragma unroll
    for (int mt = 0; mt < 2; mt++)
#pragma unroll
        for (int rh = 0; rh < 2; rh++) {
            part[mt][rh] += __shfl_xor_sync(0xffffffffu, part[mt][rh], 1);
            part[mt][rh] += __shfl_xor_sync(0xffffffffu, part[mt][rh], 2);
        }
    if (tig == 0) {
        const float b4v = __ldg(b4 + t);
#pragma unroll
        for (int mt = 0; mt < 2; mt++)
#pragma unroll
            for (int rh = 0; rh < 2; rh++) {
                const int row = wm * 32 + mt * 16 + rh * 8 + g;
                if (row < nact) {
                    const int id = sids[row];
                    const int mol = g_is64 ? batch32[2 * id] : batch32[id];
                    atomicAdd(&out[mol], part[mt][rh] + (wn == 0 ? b4v : 0.0f));
                }
            }
    }
}

// ---------------- launch ----------------
extern "C" void kernel_launch(void* const* d_in, const int* in_sizes, int n_in,
                              void* d_out, int out_size) {
    const int*   z     = (const int*)  d_in[0];
    const float* feat  = (const float*)d_in[1];
    const int*   batch = (const int*)  d_in[2];
    const float* W1 = (const float*)d_in[4];
    const float* b1 = (const float*)d_in[5];
    const float* W2 = (const float*)d_in[6];
    const float* b2 = (const float*)d_in[7];
    const float* W3 = (const float*)d_in[8];
    const float* b3 = (const float*)d_in[9];
    const float* W4 = (const float*)d_in[10];
    const float* b4 = (const float*)d_in[11];
    float* out = (float*)d_out;

    cudaFuncSetAttribute(k_gemm1, cudaFuncAttributeMaxDynamicSharedMemorySize, G1_SM_TOTAL);
    cudaFuncSetAttribute(k_gemm2, cudaFuncAttributeMaxDynamicSharedMemorySize, G2_SM_TOTAL);
    cudaFuncSetAttribute(k_gemm3, cudaFuncAttributeMaxDynamicSharedMemorySize, G3_SM_TOTAL);

    const int initN = (out_size > PAD_MAX) ? out_size : PAD_MAX;
    const int prepN = 5 * H1 * KPAD / 4 + 5 * H2 * H1 / 4 + 5 * H3 * H2 / 4;
    const int cpN = (prepN > N_ATOMS) ? prepN : N_ATOMS;

    k_init<<<(initN + 255) / 256, 256>>>(z, out, out_size);            // 1
    dim3 cpg((cpN + 255) / 256, 2);
    k_count_prep<<<cpg, 256>>>(z, W1, W2, W3);                         // 2
    k_scatter<<<(N_ATOMS + 255) / 256, 256>>>();                       // 3

    dim3 grid1(2, NT_MAX, 5);
    k_gemm1<<<grid1, TPB1, G1_SM_TOTAL>>>(feat, b1);                   // 4 <- profiled
    dim3 grid2(2, NT_MAX, 5);
    k_gemm2<<<grid2, TPB1, G2_SM_TOTAL>>>(b2);                         // 5
    dim3 grid3(NT_MAX, 5);
    k_gemm3<<<grid3, TPB1, G3_SM_TOTAL>>>(batch, b3, W4, b4, out);     // 6
}